// round 4
// baseline (speedup 1.0000x reference)
#include <cuda_runtime.h>
#include <cuda_fp16.h>
#include <cstdint>
#include <math_constants.h>

// ---------------------------------------------------------------------------
// Device scratch (static: allocation-free)
// ---------------------------------------------------------------------------
__device__ __half g_a [65536 * 512];   // A' pixel-major [m][k'=512] (xh,xl interleaved)
__device__ __half g_b1[512 * 512];     // B1' [p][k'] = (bh,bl) interleaved
__device__ __half g_b2[512 * 512];     // B2' [p][k'] = (bl,bh) interleaved
__device__ float  g_pnf[512 * 256];    // normalized protos fp32 (for fixup)
__device__ int    g_idx[65536];        // per-pixel argmax
__device__ int    g_fixlist[65536];
__device__ int    g_nfix;

__device__ __forceinline__ uint32_t smem_u32(const void* p) {
    uint32_t a;
    asm("{ .reg .u64 t; cvta.to.shared.u64 t, %1; cvt.u32.u64 %0, t; }"
        : "=r"(a) : "l"(p));
    return a;
}
__device__ __forceinline__ void cpa16(uint32_t dst, const void* src) {
    asm volatile("cp.async.cg.shared.global [%0], [%1], 16;"
                 :: "r"(dst), "l"(src));
}
#define LDSM_X4(r0,r1,r2,r3,addr) \
    asm volatile("ldmatrix.sync.aligned.m8n8.x4.shared.b16 {%0,%1,%2,%3}, [%4];" \
        : "=r"(r0),"=r"(r1),"=r"(r2),"=r"(r3) : "r"(addr))
#define LDSM_X2(r0,r1,addr) \
    asm volatile("ldmatrix.sync.aligned.m8n8.x2.shared.b16 {%0,%1}, [%2];" \
        : "=r"(r0),"=r"(r1) : "r"(addr))
#define MMA16816(d,a,b) \
    asm volatile("mma.sync.aligned.m16n8k16.row.col.f32.f16.f16.f32 " \
        "{%0,%1,%2,%3},{%4,%5,%6,%7},{%8,%9},{%0,%1,%2,%3};" \
        : "+f"(d[0]),"+f"(d[1]),"+f"(d[2]),"+f"(d[3]) \
        : "r"(a[0]),"r"(a[1]),"r"(a[2]),"r"(a[3]),"r"(b[0]),"r"(b[1]))

// ---------------------------------------------------------------------------
// Prep 1: normalize protos; build B1'/B2' fp16 splits; keep fp32 copy; reset ctr
// ---------------------------------------------------------------------------
__global__ void proto_prep_kernel(const float* __restrict__ proto) {
    __shared__ float sred[8];
    const int p = blockIdx.x, c = threadIdx.x;
    float v = proto[(p << 8) + c];
    float ss = v * v;
    #pragma unroll
    for (int s = 16; s >= 1; s >>= 1) ss += __shfl_xor_sync(0xffffffffu, ss, s);
    if ((c & 31) == 0) sred[c >> 5] = ss;
    __syncthreads();
    float tot = 0.f;
    #pragma unroll
    for (int w = 0; w < 8; ++w) tot += sred[w];
    const float pn = v / fmaxf(sqrtf(tot), 1e-12f);
    g_pnf[(p << 8) + c] = pn;
    __half bh = __float2half(pn);
    __half bl = __float2half(pn - __half2float(bh));
    reinterpret_cast<__half2*>(g_b1)[(p << 8) + c] = __halves2half2(bh, bl);
    reinterpret_cast<__half2*>(g_b2)[(p << 8) + c] = __halves2half2(bl, bh);
    if (p == 0 && c == 0) g_nfix = 0;
}

// ---------------------------------------------------------------------------
// Prep 2: transpose x [b][c][m] -> A' [m][k'] fp16 split pairs
// ---------------------------------------------------------------------------
__global__ void xsplit_kernel(const float* __restrict__ x) {
    __shared__ float t[32][33];
    const int b = blockIdx.z, c0 = blockIdx.x << 5, m0 = blockIdx.y << 5;
    const int tx = threadIdx.x & 31, ty = threadIdx.x >> 5;
    #pragma unroll
    for (int i = 0; i < 4; ++i) {
        int c = ty + (i << 3);
        t[c][tx] = x[b * 262144 + (c0 + c) * 1024 + m0 + tx];
    }
    __syncthreads();
    #pragma unroll
    for (int i = 0; i < 4; ++i) {
        int m = ty + (i << 3);
        float v = t[tx][m];
        __half h = __float2half(v);
        __half l = __float2half(v - __half2float(h));
        reinterpret_cast<__half2*>(g_a)[(b * 1024 + m0 + m) * 256 + c0 + tx] =
            __halves2half2(h, l);
    }
}

// ---------------------------------------------------------------------------
// Main: 512 blocks x 128 pixels. A (128x512 fp16) staged once (128KB smem);
// B1/B2 slices (64 k') double-buffered. mma m16n8k16, fp32 acc, top-2 epilogue.
// ---------------------------------------------------------------------------
__global__ __launch_bounds__(256, 1)
void protomatch_mma(float* __restrict__ out, long long out_size)
{
    extern __shared__ char dsm[];
    const uint32_t dynb = smem_u32(dsm);
    const uint32_t base = (dynb + 1023u) & ~1023u;
    char* base_g = dsm + (base - dynb);
    const uint32_t Asm = base;            // 131072 bytes (8 slices x 16KB)
    const uint32_t Bsm = base + 131072u;  // 65536 bytes (2 bufs x [B1 16K|B2 16K])

    const int tid = threadIdx.x, lane = tid & 31, wid = tid >> 5;
    const int warp_m = wid & 3, warp_n = wid >> 2;
    const int m0 = blockIdx.x << 7;

    // ---- stage all of A (128 rows x 512 k' fp16) ----
    const char* Ag = reinterpret_cast<const char*>(g_a);
    #pragma unroll
    for (int i = 0; i < 32; ++i) {
        int u = tid + (i << 8);          // 0..8191
        int s = u >> 10;                 // slice 0..7
        int r = (u >> 3) & 127;          // row 0..127
        int c = u & 7;                   // 16B col 0..7
        uint32_t o = (uint32_t)(r << 7) + (uint32_t)(c << 4);
        cpa16(Asm + (s << 14) + (o ^ ((o >> 3) & 0x70)),
              Ag + (size_t)(m0 + r) * 1024 + (s << 7) + (c << 4));
    }
    asm volatile("cp.async.commit_group;");

    // ---- prime B slice t=0 ----
    const char* B1g = reinterpret_cast<const char*>(g_b1);
    const char* B2g = reinterpret_cast<const char*>(g_b2);
    {
        #pragma unroll
        for (int i = 0; i < 8; ++i) {
            int u = tid + (i << 8);
            int mat = u >> 10, r = (u >> 3) & 127, c = u & 7;
            uint32_t o = (uint32_t)(r << 7) + (uint32_t)(c << 4);
            const char* src = (mat ? B2g : B1g) + (size_t)r * 1024 + (c << 4);
            cpa16(Bsm + (mat << 14) + (o ^ ((o >> 3) & 0x70)), src);
        }
        asm volatile("cp.async.commit_group;");
    }

    // per-lane ldmatrix address components
    uint32_t aoff[2], aswz[2];
    #pragma unroll
    for (int mt = 0; mt < 2; ++mt) {
        int rowA = warp_m * 32 + mt * 16 + (lane & 15);
        aoff[mt] = (uint32_t)rowA << 7;
        aswz[mt] = (uint32_t)(rowA & 7);
    }
    const uint32_t alc = (uint32_t)(lane >> 4);        // 0/1
    uint32_t boff[8], bswz[8];
    #pragma unroll
    for (int nt = 0; nt < 8; ++nt) {
        int rowB = warp_n * 64 + nt * 8 + (lane & 7);
        boff[nt] = (uint32_t)rowB << 7;
        bswz[nt] = (uint32_t)(rowB & 7);
    }
    const uint32_t blc = (uint32_t)((lane >> 3) & 1);  // 0/1

    float acc[2][8][4];
    float t1v[4], t2v[4];
    int   t1i[4];
    #pragma unroll
    for (int s = 0; s < 4; ++s) { t1v[s] = -CUDART_INF_F; t2v[s] = -CUDART_INF_F; t1i[s] = 0; }

    for (int t = 0; t < 32; ++t) {
        const int pc = t >> 3, ks = t & 7;
        if (ks == 0) {
            #pragma unroll
            for (int i = 0; i < 2; ++i)
                #pragma unroll
                for (int j = 0; j < 8; ++j)
                    #pragma unroll
                    for (int q = 0; q < 4; ++q) acc[i][j][q] = 0.f;
        }
        // prefetch B slice t+1 into buf (t+1)&1
        if (t + 1 < 32) {
            int pc1 = (t + 1) >> 3, ks1 = (t + 1) & 7;
            uint32_t dst = Bsm + (uint32_t)((t + 1) & 1) * 32768u;
            #pragma unroll
            for (int i = 0; i < 8; ++i) {
                int u = tid + (i << 8);
                int mat = u >> 10, r = (u >> 3) & 127, c = u & 7;
                uint32_t o = (uint32_t)(r << 7) + (uint32_t)(c << 4);
                const char* src = (mat ? B2g : B1g)
                    + (size_t)(pc1 * 128 + r) * 1024 + (ks1 << 7) + (c << 4);
                cpa16(dst + (mat << 14) + (o ^ ((o >> 3) & 0x70)), src);
            }
            asm volatile("cp.async.commit_group;");
            asm volatile("cp.async.wait_group 1;");
        } else {
            asm volatile("cp.async.wait_group 0;");
        }
        __syncthreads();

        const uint32_t Ab = Asm + ((uint32_t)ks << 14);
        const uint32_t Bb = Bsm + (uint32_t)(t & 1) * 32768u;

        #pragma unroll
        for (int k16 = 0; k16 < 4; ++k16) {
            uint32_t ra[2][4];
            #pragma unroll
            for (int mt = 0; mt < 2; ++mt) {
                uint32_t c16 = (uint32_t)(k16 << 1) + alc;
                uint32_t addr = Ab + aoff[mt] + ((c16 ^ aswz[mt]) << 4);
                LDSM_X4(ra[mt][0], ra[mt][1], ra[mt][2], ra[mt][3], addr);
            }
            #pragma unroll
            for (int nt = 0; nt < 8; ++nt) {
                uint32_t c16 = (uint32_t)(k16 << 1) + blc;
                uint32_t col = ((c16 ^ bswz[nt]) << 4);
                uint32_t rb1[2], rb2[2];
                LDSM_X2(rb1[0], rb1[1], Bb + boff[nt] + col);
                LDSM_X2(rb2[0], rb2[1], Bb + 16384u + boff[nt] + col);
                MMA16816(acc[0][nt], ra[0], rb1);
                MMA16816(acc[1][nt], ra[1], rb1);
                MMA16816(acc[0][nt], ra[0], rb2);
                MMA16816(acc[1][nt], ra[1], rb2);
            }
        }
        __syncthreads();   // all warps done with buf t&1 before refill

        if (ks == 7) {     // fold chunk into running top-2
            #pragma unroll
            for (int mt = 0; mt < 2; ++mt)
                #pragma unroll
                for (int rh = 0; rh < 2; ++rh) {
                    int s = mt * 2 + rh;
                    #pragma unroll
                    for (int nt = 0; nt < 8; ++nt)
                        #pragma unroll
                        for (int e = 0; e < 2; ++e) {
                            float v = acc[mt][nt][rh * 2 + e];
                            int col = (pc << 7) + (warp_n << 6) + (nt << 3)
                                    + ((lane & 3) << 1) + e;
                            if (v > t1v[s]) { t2v[s] = t1v[s]; t1v[s] = v; t1i[s] = col; }
                            else if (v > t2v[s]) t2v[s] = v;
                        }
                }
        }
    }

    // ---- cross-lane/warp reduction via smem (reuse A region) ----
    float* sv1 = reinterpret_cast<float*>(base_g);
    int*   si1 = reinterpret_cast<int*>(base_g + 4096);
    float* sv2 = reinterpret_cast<float*>(base_g + 8192);
    #pragma unroll
    for (int mt = 0; mt < 2; ++mt)
        #pragma unroll
        for (int rh = 0; rh < 2; ++rh) {
            int s = mt * 2 + rh;
            int row = warp_m * 32 + mt * 16 + rh * 8 + (lane >> 2);
            int cand = (warp_n << 2) + (lane & 3);
            sv1[row * 8 + cand] = t1v[s];
            si1[row * 8 + cand] = t1i[s];
            sv2[row * 8 + cand] = t2v[s];
        }
    __syncthreads();

    if (tid < 128) {
        float v1 = -CUDART_INF_F, v2 = -CUDART_INF_F;
        int i1 = 0x7fffffff;
        #pragma unroll
        for (int c = 0; c < 8; ++c) {
            float cv1 = sv1[tid * 8 + c], cv2 = sv2[tid * 8 + c];
            int   ci1 = si1[tid * 8 + c];
            if (cv1 > v1 || (cv1 == v1 && ci1 < i1)) {
                v2 = fmaxf(v1, cv2); v1 = cv1; i1 = ci1;
            } else {
                v2 = fmaxf(v2, cv1);
            }
        }
        const int m = m0 + tid;
        g_idx[m] = i1;
        if (out_size > 16777216LL) out[16777216 + m] = (float)i1;
        if (v1 - v2 < 1e-3f) {
            int pos = atomicAdd(&g_nfix, 1);
            g_fixlist[pos] = m;
        }
    }
}

// ---------------------------------------------------------------------------
// Fixup: exact fp32 argmax for flagged (near-tie) pixels
// ---------------------------------------------------------------------------
__global__ __launch_bounds__(256)
void fixup_kernel(const float* __restrict__ x, float* __restrict__ out,
                  long long out_size)
{
    __shared__ float xs[256];
    __shared__ float rv[8];
    __shared__ int   ri[8];
    const int tid = threadIdx.x;
    for (int e = blockIdx.x; e < g_nfix; e += gridDim.x) {
        const int m = g_fixlist[e];
        const int b = m >> 10, mi = m & 1023;
        xs[tid] = x[b * 262144 + tid * 1024 + mi];
        __syncthreads();
        float bv = -CUDART_INF_F; int bi = 0;
        #pragma unroll
        for (int h = 0; h < 2; ++h) {
            int p = tid + (h << 8);
            const float* pr = g_pnf + (p << 8);
            float s = 0.f;
            #pragma unroll 8
            for (int c = 0; c < 256; ++c) s = fmaf(xs[c], pr[c], s);
            if (s > bv || (s == bv && p < bi)) { bv = s; bi = p; }
        }
        #pragma unroll
        for (int sft = 16; sft >= 1; sft >>= 1) {
            float ov = __shfl_xor_sync(0xffffffffu, bv, sft);
            int   oi = __shfl_xor_sync(0xffffffffu, bi, sft);
            if (ov > bv || (ov == bv && oi < bi)) { bv = ov; bi = oi; }
        }
        if ((tid & 31) == 0) { rv[tid >> 5] = bv; ri[tid >> 5] = bi; }
        __syncthreads();
        if (tid == 0) {
            float fv = rv[0]; int fi = ri[0];
            #pragma unroll
            for (int w = 1; w < 8; ++w)
                if (rv[w] > fv || (rv[w] == fv && ri[w] < fi)) { fv = rv[w]; fi = ri[w]; }
            g_idx[m] = fi;
            if (out_size > 16777216LL) out[16777216 + m] = (float)fi;
        }
        __syncthreads();
    }
}

// ---------------------------------------------------------------------------
// Gather: recon[b,c,h,w] = proto[idx[pixel]][c], coalesced
// ---------------------------------------------------------------------------
__global__ __launch_bounds__(256)
void gather_kernel(const float* __restrict__ proto, float* __restrict__ out)
{
    __shared__ int sIdx[128];
    const int tid = threadIdx.x;
    const int m0 = blockIdx.x << 7, b = m0 >> 10, n0 = m0 & 1023;
    if (tid < 128) sIdx[tid] = g_idx[m0 + tid];
    __syncthreads();
    const int n4 = tid & 31, co = tid >> 5;
    const float* r0 = proto + (sIdx[(n4 << 2) + 0] << 8);
    const float* r1 = proto + (sIdx[(n4 << 2) + 1] << 8);
    const float* r2 = proto + (sIdx[(n4 << 2) + 2] << 8);
    const float* r3 = proto + (sIdx[(n4 << 2) + 3] << 8);
    float4* Og = reinterpret_cast<float4*>(out) + (b * 65536 + (n0 >> 2) + n4);
    #pragma unroll 4
    for (int c = co; c < 256; c += 8)
        Og[c * 256] = make_float4(r0[c], r1[c], r2[c], r3[c]);
}

// ---------------------------------------------------------------------------
extern "C" void kernel_launch(void* const* d_in, const int* in_sizes, int n_in,
                              void* d_out, int out_size)
{
    const float* x     = (const float*)d_in[0];
    const float* proto = (const float*)d_in[1];
    if (n_in >= 2 && in_sizes[0] == 512 * 256 && in_sizes[1] != 512 * 256) {
        proto = (const float*)d_in[0];
        x     = (const float*)d_in[1];
    }
    float* out = (float*)d_out;

    proto_prep_kernel<<<512, 256>>>(proto);
    xsplit_kernel<<<dim3(8, 32, 64), 256>>>(x);

    cudaFuncSetAttribute(protomatch_mma,
                         cudaFuncAttributeMaxDynamicSharedMemorySize, 197632);
    protomatch_mma<<<512, 256, 197632>>>(out, (long long)out_size);

    fixup_kernel<<<64, 256>>>(x, out, (long long)out_size);
    gather_kernel<<<512, 256>>>(proto, out);
}

// round 5
// speedup vs baseline: 1.5814x; 1.5814x over previous
#include <cuda_runtime.h>
#include <cuda_fp16.h>
#include <cstdint>
#include <math_constants.h>

// ---------------------------------------------------------------------------
// Device scratch (static: allocation-free)
// ---------------------------------------------------------------------------
__device__ __half g_a [65536 * 512];   // A' pixel-major [m][k'=512] (xh,xl interleaved)
__device__ __half g_b1[512 * 512];     // B1' [p][k'] = (bh,bl) interleaved
__device__ __half g_b2[512 * 512];     // B2' [p][k'] = (bl,bh) interleaved
__device__ float  g_pnf[512 * 256];    // normalized protos fp32 (for fixup)
__device__ int    g_idx[65536];        // per-pixel argmax
__device__ int    g_fixlist[65536];
__device__ int    g_nfix;

__device__ __forceinline__ uint32_t smem_u32(const void* p) {
    uint32_t a;
    asm("{ .reg .u64 t; cvta.to.shared.u64 t, %1; cvt.u32.u64 %0, t; }"
        : "=r"(a) : "l"(p));
    return a;
}
__device__ __forceinline__ void cpa16(uint32_t dst, const void* src) {
    asm volatile("cp.async.cg.shared.global [%0], [%1], 16;"
                 :: "r"(dst), "l"(src));
}
#define LDSM_X4(r0,r1,r2,r3,addr) \
    asm volatile("ldmatrix.sync.aligned.m8n8.x4.shared.b16 {%0,%1,%2,%3}, [%4];" \
        : "=r"(r0),"=r"(r1),"=r"(r2),"=r"(r3) : "r"(addr))
#define MMA16816(d,a,b) \
    asm volatile("mma.sync.aligned.m16n8k16.row.col.f32.f16.f16.f32 " \
        "{%0,%1,%2,%3},{%4,%5,%6,%7},{%8,%9},{%0,%1,%2,%3};" \
        : "+f"(d[0]),"+f"(d[1]),"+f"(d[2]),"+f"(d[3]) \
        : "r"(a[0]),"r"(a[1]),"r"(a[2]),"r"(a[3]),"r"(b[0]),"r"(b[1]))

// ---------------------------------------------------------------------------
// Prep 1: normalize protos; build B1'/B2' fp16 splits; keep fp32 copy; reset ctr
// ---------------------------------------------------------------------------
__global__ void proto_prep_kernel(const float* __restrict__ proto) {
    __shared__ float sred[8];
    const int p = blockIdx.x, c = threadIdx.x;
    float v = proto[(p << 8) + c];
    float ss = v * v;
    #pragma unroll
    for (int s = 16; s >= 1; s >>= 1) ss += __shfl_xor_sync(0xffffffffu, ss, s);
    if ((c & 31) == 0) sred[c >> 5] = ss;
    __syncthreads();
    float tot = 0.f;
    #pragma unroll
    for (int w = 0; w < 8; ++w) tot += sred[w];
    const float pn = v / fmaxf(sqrtf(tot), 1e-12f);
    g_pnf[(p << 8) + c] = pn;
    __half bh = __float2half(pn);
    __half bl = __float2half(pn - __half2float(bh));
    reinterpret_cast<__half2*>(g_b1)[(p << 8) + c] = __halves2half2(bh, bl);
    reinterpret_cast<__half2*>(g_b2)[(p << 8) + c] = __halves2half2(bl, bh);
    if (p == 0 && c == 0) g_nfix = 0;
}

// ---------------------------------------------------------------------------
// Prep 2: transpose x [b][c][m] -> A' [m][k'] fp16 split pairs
// ---------------------------------------------------------------------------
__global__ void xsplit_kernel(const float* __restrict__ x) {
    __shared__ float t[32][33];
    const int b = blockIdx.z, c0 = blockIdx.x << 5, m0 = blockIdx.y << 5;
    const int tx = threadIdx.x & 31, ty = threadIdx.x >> 5;
    #pragma unroll
    for (int i = 0; i < 4; ++i) {
        int c = ty + (i << 3);
        t[c][tx] = x[b * 262144 + (c0 + c) * 1024 + m0 + tx];
    }
    __syncthreads();
    #pragma unroll
    for (int i = 0; i < 4; ++i) {
        int m = ty + (i << 3);
        float v = t[tx][m];
        __half h = __float2half(v);
        __half l = __float2half(v - __half2float(h));
        reinterpret_cast<__half2*>(g_a)[(b * 1024 + m0 + m) * 256 + c0 + tx] =
            __halves2half2(h, l);
    }
}

// ---------------------------------------------------------------------------
// Main: 512 blocks x 128 pixels. A (128x512 fp16) staged once (128KB smem);
// B1/B2 slices (64 k') double-buffered. mma m16n8k16, fp32 acc, top-2 epilogue.
// ---------------------------------------------------------------------------
__global__ __launch_bounds__(256, 1)
void protomatch_mma(float* __restrict__ out, long long out_size)
{
    extern __shared__ char dsm[];
    const uint32_t dynb = smem_u32(dsm);
    const uint32_t base = (dynb + 1023u) & ~1023u;
    char* base_g = dsm + (base - dynb);
    const uint32_t Asm = base;            // 131072 bytes (8 slices x 16KB)
    const uint32_t Bsm = base + 131072u;  // 65536 bytes (2 bufs x [B1 16K|B2 16K])

    const int tid = threadIdx.x, lane = tid & 31, wid = tid >> 5;
    const int warp_m = wid & 3, warp_n = wid >> 2;
    const int m0 = blockIdx.x << 7;

    // ---- stage all of A (128 rows x 512 k' fp16) ----
    const char* Ag = reinterpret_cast<const char*>(g_a);
    #pragma unroll
    for (int i = 0; i < 32; ++i) {
        int u = tid + (i << 8);          // 0..8191
        int s = u >> 10;                 // slice 0..7
        int r = (u >> 3) & 127;          // row 0..127
        int c = u & 7;                   // 16B col 0..7
        uint32_t o = (uint32_t)(r << 7) + (uint32_t)(c << 4);
        cpa16(Asm + (s << 14) + (o ^ ((o >> 3) & 0x70)),
              Ag + (size_t)(m0 + r) * 1024 + (s << 7) + (c << 4));
    }
    asm volatile("cp.async.commit_group;");

    // ---- prime B slice t=0 ----
    const char* B1g = reinterpret_cast<const char*>(g_b1);
    const char* B2g = reinterpret_cast<const char*>(g_b2);
    {
        #pragma unroll
        for (int i = 0; i < 8; ++i) {
            int u = tid + (i << 8);
            int mat = u >> 10, r = (u >> 3) & 127, c = u & 7;
            uint32_t o = (uint32_t)(r << 7) + (uint32_t)(c << 4);
            const char* src = (mat ? B2g : B1g) + (size_t)r * 1024 + (c << 4);
            cpa16(Bsm + (mat << 14) + (o ^ ((o >> 3) & 0x70)), src);
        }
        asm volatile("cp.async.commit_group;");
    }

    // per-lane ldmatrix address components
    uint32_t aoff[2], aswz[2];
    #pragma unroll
    for (int mt = 0; mt < 2; ++mt) {
        int rowA = warp_m * 32 + mt * 16 + (lane & 15);
        aoff[mt] = (uint32_t)rowA << 7;
        aswz[mt] = (uint32_t)(rowA & 7);
    }
    const uint32_t alc = (uint32_t)(lane >> 4);        // 0/1

    // B x4: lanes 0-15 -> n-rows nt2*16+0..7 (two k-halves), 16-31 -> +8..15
    uint32_t boff[4], bswz[4];
    #pragma unroll
    for (int nt2 = 0; nt2 < 4; ++nt2) {
        int rowB = warp_n * 64 + nt2 * 16 + ((lane >> 4) << 3) + (lane & 7);
        boff[nt2] = (uint32_t)rowB << 7;
        bswz[nt2] = (uint32_t)(rowB & 7);
    }
    const uint32_t blc = (uint32_t)((lane >> 3) & 1);  // k-half select

    float acc[2][8][4];
    float t1v[4], t2v[4];
    int   t1i[4];
    #pragma unroll
    for (int s = 0; s < 4; ++s) { t1v[s] = -CUDART_INF_F; t2v[s] = -CUDART_INF_F; t1i[s] = 0; }

    for (int t = 0; t < 32; ++t) {
        const int pc = t >> 3, ks = t & 7;
        if (ks == 0) {
            #pragma unroll
            for (int i = 0; i < 2; ++i)
                #pragma unroll
                for (int j = 0; j < 8; ++j)
                    #pragma unroll
                    for (int q = 0; q < 4; ++q) acc[i][j][q] = 0.f;
        }
        // prefetch B slice t+1 into buf (t+1)&1
        if (t + 1 < 32) {
            int pc1 = (t + 1) >> 3, ks1 = (t + 1) & 7;
            uint32_t dst = Bsm + (uint32_t)((t + 1) & 1) * 32768u;
            #pragma unroll
            for (int i = 0; i < 8; ++i) {
                int u = tid + (i << 8);
                int mat = u >> 10, r = (u >> 3) & 127, c = u & 7;
                uint32_t o = (uint32_t)(r << 7) + (uint32_t)(c << 4);
                const char* src = (mat ? B2g : B1g)
                    + (size_t)(pc1 * 128 + r) * 1024 + (ks1 << 7) + (c << 4);
                cpa16(dst + (mat << 14) + (o ^ ((o >> 3) & 0x70)), src);
            }
            asm volatile("cp.async.commit_group;");
            asm volatile("cp.async.wait_group 1;");
        } else {
            asm volatile("cp.async.wait_group 0;");
        }
        __syncthreads();

        const uint32_t Ab = Asm + ((uint32_t)ks << 14);
        const uint32_t Bb = Bsm + (uint32_t)(t & 1) * 32768u;

        #pragma unroll
        for (int k16 = 0; k16 < 4; ++k16) {
            uint32_t ra[2][4];
            #pragma unroll
            for (int mt = 0; mt < 2; ++mt) {
                uint32_t c16 = (uint32_t)(k16 << 1) + alc;
                uint32_t addr = Ab + aoff[mt] + ((c16 ^ aswz[mt]) << 4);
                LDSM_X4(ra[mt][0], ra[mt][1], ra[mt][2], ra[mt][3], addr);
            }
            #pragma unroll
            for (int nt2 = 0; nt2 < 4; ++nt2) {
                uint32_t c16 = (uint32_t)(k16 << 1) + blc;
                uint32_t col = ((c16 ^ bswz[nt2]) << 4);
                uint32_t rb1[4], rb2[4];
                LDSM_X4(rb1[0], rb1[1], rb1[2], rb1[3], Bb + boff[nt2] + col);
                LDSM_X4(rb2[0], rb2[1], rb2[2], rb2[3], Bb + 16384u + boff[nt2] + col);
                MMA16816(acc[0][2*nt2+0], ra[0], (rb1 + 0));
                MMA16816(acc[1][2*nt2+0], ra[1], (rb1 + 0));
                MMA16816(acc[0][2*nt2+1], ra[0], (rb1 + 2));
                MMA16816(acc[1][2*nt2+1], ra[1], (rb1 + 2));
                MMA16816(acc[0][2*nt2+0], ra[0], (rb2 + 0));
                MMA16816(acc[1][2*nt2+0], ra[1], (rb2 + 0));
                MMA16816(acc[0][2*nt2+1], ra[0], (rb2 + 2));
                MMA16816(acc[1][2*nt2+1], ra[1], (rb2 + 2));
            }
        }
        __syncthreads();   // all warps done with buf t&1 before refill

        if (ks == 7) {     // fold chunk into running top-2
            #pragma unroll
            for (int mt = 0; mt < 2; ++mt)
                #pragma unroll
                for (int rh = 0; rh < 2; ++rh) {
                    int s = mt * 2 + rh;
                    #pragma unroll
                    for (int nt = 0; nt < 8; ++nt)
                        #pragma unroll
                        for (int e = 0; e < 2; ++e) {
                            float v = acc[mt][nt][rh * 2 + e];
                            int col = (pc << 7) + (warp_n << 6) + (nt << 3)
                                    + ((lane & 3) << 1) + e;
                            if (v > t1v[s]) { t2v[s] = t1v[s]; t1v[s] = v; t1i[s] = col; }
                            else if (v > t2v[s]) t2v[s] = v;
                        }
                }
        }
    }

    // ---- cross-lane/warp reduction via smem (reuse A region) ----
    float* sv1 = reinterpret_cast<float*>(base_g);
    int*   si1 = reinterpret_cast<int*>(base_g + 4096);
    float* sv2 = reinterpret_cast<float*>(base_g + 8192);
    #pragma unroll
    for (int mt = 0; mt < 2; ++mt)
        #pragma unroll
        for (int rh = 0; rh < 2; ++rh) {
            int s = mt * 2 + rh;
            int row = warp_m * 32 + mt * 16 + rh * 8 + (lane >> 2);
            int cand = (warp_n << 2) + (lane & 3);
            sv1[row * 8 + cand] = t1v[s];
            si1[row * 8 + cand] = t1i[s];
            sv2[row * 8 + cand] = t2v[s];
        }
    __syncthreads();

    if (tid < 128) {
        float v1 = -CUDART_INF_F, v2 = -CUDART_INF_F;
        int i1 = 0x7fffffff;
        #pragma unroll
        for (int c = 0; c < 8; ++c) {
            float cv1 = sv1[tid * 8 + c], cv2 = sv2[tid * 8 + c];
            int   ci1 = si1[tid * 8 + c];
            if (cv1 > v1 || (cv1 == v1 && ci1 < i1)) {
                v2 = fmaxf(v1, cv2); v1 = cv1; i1 = ci1;
            } else {
                v2 = fmaxf(v2, cv1);
            }
        }
        const int m = m0 + tid;
        g_idx[m] = i1;
        if (out_size > 16777216LL) out[16777216 + m] = (float)i1;
        if (v1 - v2 < 1e-4f) {
            int pos = atomicAdd(&g_nfix, 1);
            g_fixlist[pos] = m;
        }
    }
}

// ---------------------------------------------------------------------------
// Fixup: exact fp32 argmax for flagged pixels, 8 entries batched per block
// ---------------------------------------------------------------------------
__global__ __launch_bounds__(256)
void fixup_kernel(const float* __restrict__ x, float* __restrict__ out,
                  long long out_size)
{
    __shared__ __align__(16) float xs[8][260];
    __shared__ float rbv[8][8];
    __shared__ int   rbi[8][8];
    const int tid = threadIdx.x, lane = tid & 31, wid = tid >> 5;
    const int nfix = g_nfix;

    for (int g0 = blockIdx.x * 8; g0 < nfix; g0 += gridDim.x * 8) {
        const int ne = min(8, nfix - g0);
        for (int i = tid; i < (ne << 8); i += 256) {
            int e = i >> 8, c = i & 255;
            int m = g_fixlist[g0 + e];
            xs[e][c] = x[(m >> 10) * 262144 + c * 1024 + (m & 1023)];
        }
        __syncthreads();

        float bv[8]; int bi[8];
        #pragma unroll
        for (int e = 0; e < 8; ++e) { bv[e] = -CUDART_INF_F; bi[e] = 0; }

        #pragma unroll
        for (int h = 0; h < 2; ++h) {
            const int p = tid + (h << 8);
            const float4* pr = reinterpret_cast<const float4*>(g_pnf + (p << 8));
            float acc[8];
            #pragma unroll
            for (int e = 0; e < 8; ++e) acc[e] = 0.f;
            #pragma unroll 4
            for (int c4 = 0; c4 < 64; ++c4) {
                float4 pv = pr[c4];
                #pragma unroll
                for (int e = 0; e < 8; ++e) {
                    float4 xv = reinterpret_cast<const float4*>(xs[e])[c4];
                    acc[e] = fmaf(pv.x, xv.x, acc[e]);
                    acc[e] = fmaf(pv.y, xv.y, acc[e]);
                    acc[e] = fmaf(pv.z, xv.z, acc[e]);
                    acc[e] = fmaf(pv.w, xv.w, acc[e]);
                }
            }
            #pragma unroll
            for (int e = 0; e < 8; ++e)
                if (acc[e] > bv[e]) { bv[e] = acc[e]; bi[e] = p; }  // ascending p
        }

        #pragma unroll
        for (int e = 0; e < 8; ++e) {
            float v = bv[e]; int ix = bi[e];
            #pragma unroll
            for (int s = 16; s >= 1; s >>= 1) {
                float ov = __shfl_xor_sync(0xffffffffu, v, s);
                int   oi = __shfl_xor_sync(0xffffffffu, ix, s);
                if (ov > v || (ov == v && oi < ix)) { v = ov; ix = oi; }
            }
            if (lane == 0) { rbv[e][wid] = v; rbi[e][wid] = ix; }
        }
        __syncthreads();

        if (tid < ne) {
            float fv = rbv[tid][0]; int fi = rbi[tid][0];
            #pragma unroll
            for (int w = 1; w < 8; ++w)
                if (rbv[tid][w] > fv || (rbv[tid][w] == fv && rbi[tid][w] < fi)) {
                    fv = rbv[tid][w]; fi = rbi[tid][w];
                }
            const int m = g_fixlist[g0 + tid];
            g_idx[m] = fi;
            if (out_size > 16777216LL) out[16777216 + m] = (float)fi;
        }
        __syncthreads();
    }
}

// ---------------------------------------------------------------------------
// Gather: recon[b,c,h,w] = proto[idx[pixel]][c], coalesced
// ---------------------------------------------------------------------------
__global__ __launch_bounds__(256)
void gather_kernel(const float* __restrict__ proto, float* __restrict__ out)
{
    __shared__ int sIdx[128];
    const int tid = threadIdx.x;
    const int m0 = blockIdx.x << 7, b = m0 >> 10, n0 = m0 & 1023;
    if (tid < 128) sIdx[tid] = g_idx[m0 + tid];
    __syncthreads();
    const int n4 = tid & 31, co = tid >> 5;
    const float* r0 = proto + (sIdx[(n4 << 2) + 0] << 8);
    const float* r1 = proto + (sIdx[(n4 << 2) + 1] << 8);
    const float* r2 = proto + (sIdx[(n4 << 2) + 2] << 8);
    const float* r3 = proto + (sIdx[(n4 << 2) + 3] << 8);
    float4* Og = reinterpret_cast<float4*>(out) + (b * 65536 + (n0 >> 2) + n4);
    #pragma unroll 4
    for (int c = co; c < 256; c += 8)
        Og[c * 256] = make_float4(r0[c], r1[c], r2[c], r3[c]);
}

// ---------------------------------------------------------------------------
extern "C" void kernel_launch(void* const* d_in, const int* in_sizes, int n_in,
                              void* d_out, int out_size)
{
    const float* x     = (const float*)d_in[0];
    const float* proto = (const float*)d_in[1];
    if (n_in >= 2 && in_sizes[0] == 512 * 256 && in_sizes[1] != 512 * 256) {
        proto = (const float*)d_in[0];
        x     = (const float*)d_in[1];
    }
    float* out = (float*)d_out;

    proto_prep_kernel<<<512, 256>>>(proto);
    xsplit_kernel<<<dim3(8, 32, 64), 256>>>(x);

    cudaFuncSetAttribute(protomatch_mma,
                         cudaFuncAttributeMaxDynamicSharedMemorySize, 197632);
    protomatch_mma<<<512, 256, 197632>>>(out, (long long)out_size);

    fixup_kernel<<<128, 256>>>(x, out, (long long)out_size);
    gather_kernel<<<512, 256>>>(proto, out);
}

// round 6
// speedup vs baseline: 1.5981x; 1.0105x over previous
#include <cuda_runtime.h>
#include <cuda_fp16.h>
#include <cstdint>
#include <math_constants.h>

// ---------------------------------------------------------------------------
// Device scratch (static: allocation-free)
// ---------------------------------------------------------------------------
__device__ __half g_a [65536 * 512];   // A pixel-major [m][ cols 0-255 = xh, 256-511 = xl ]
__device__ __half g_bh[512 * 256];     // normalized proto hi [p][c]
__device__ __half g_bl[512 * 256];     // normalized proto lo [p][c]
__device__ float  g_pnf[512 * 256];    // normalized protos fp32 (for fixup)
__device__ int    g_idx[65536];        // per-pixel argmax
__device__ int    g_fixlist[65536];
__device__ int    g_nfix;

__device__ __forceinline__ uint32_t smem_u32(const void* p) {
    uint32_t a;
    asm("{ .reg .u64 t; cvta.to.shared.u64 t, %1; cvt.u32.u64 %0, t; }"
        : "=r"(a) : "l"(p));
    return a;
}
__device__ __forceinline__ void cpa16(uint32_t dst, const void* src) {
    asm volatile("cp.async.cg.shared.global [%0], [%1], 16;"
                 :: "r"(dst), "l"(src));
}
#define LDSM_X4(r0,r1,r2,r3,addr) \
    asm volatile("ldmatrix.sync.aligned.m8n8.x4.shared.b16 {%0,%1,%2,%3}, [%4];" \
        : "=r"(r0),"=r"(r1),"=r"(r2),"=r"(r3) : "r"(addr))
#define MMA16816(d,a,b) \
    asm volatile("mma.sync.aligned.m16n8k16.row.col.f32.f16.f16.f32 " \
        "{%0,%1,%2,%3},{%4,%5,%6,%7},{%8,%9},{%0,%1,%2,%3};" \
        : "+f"(d[0]),"+f"(d[1]),"+f"(d[2]),"+f"(d[3]) \
        : "r"(a[0]),"r"(a[1]),"r"(a[2]),"r"(a[3]),"r"(b[0]),"r"(b[1]))

// ---------------------------------------------------------------------------
// Prep 1: normalize protos -> fp16 hi/lo banks + fp32 copy; reset fix counter
// ---------------------------------------------------------------------------
__global__ void proto_prep_kernel(const float* __restrict__ proto) {
    __shared__ float sred[8];
    const int p = blockIdx.x, c = threadIdx.x;
    float v = proto[(p << 8) + c];
    float ss = v * v;
    #pragma unroll
    for (int s = 16; s >= 1; s >>= 1) ss += __shfl_xor_sync(0xffffffffu, ss, s);
    if ((c & 31) == 0) sred[c >> 5] = ss;
    __syncthreads();
    float tot = 0.f;
    #pragma unroll
    for (int w = 0; w < 8; ++w) tot += sred[w];
    const float pn = v / fmaxf(sqrtf(tot), 1e-12f);
    g_pnf[(p << 8) + c] = pn;
    __half bh = __float2half(pn);
    g_bh[(p << 8) + c] = bh;
    g_bl[(p << 8) + c] = __float2half(pn - __half2float(bh));
    if (p == 0 && c == 0) g_nfix = 0;
}

// ---------------------------------------------------------------------------
// Prep 2: transpose x [b][c][m] -> A [m][xh(0..255) | xl(256..511)] fp16
// ---------------------------------------------------------------------------
__global__ void xsplit_kernel(const float* __restrict__ x) {
    __shared__ float t[32][33];
    const int b = blockIdx.z, c0 = blockIdx.x << 5, m0 = blockIdx.y << 5;
    const int tx = threadIdx.x & 31, ty = threadIdx.x >> 5;
    #pragma unroll
    for (int i = 0; i < 4; ++i) {
        int c = ty + (i << 3);
        t[c][tx] = x[b * 262144 + (c0 + c) * 1024 + m0 + tx];
    }
    __syncthreads();
    #pragma unroll
    for (int i = 0; i < 4; ++i) {
        int m = ty + (i << 3);
        float v = t[tx][m];
        __half h = __float2half(v);
        __half l = __float2half(v - __half2float(h));
        size_t row = (size_t)(b * 1024 + m0 + m) << 9;
        g_a[row + c0 + tx]       = h;
        g_a[row + 256 + c0 + tx] = l;
    }
}

// ---------------------------------------------------------------------------
// B slice loader: 128 protos x 64 k fp16 = 16KB into buf (t%3), SW128 swizzle
// slice s of proto-chunk pc: s 0-7 -> bh (k-chunk s&3), s 8-11 -> bl (k-chunk s-8)
// ---------------------------------------------------------------------------
__device__ __forceinline__ void load_bslice(uint32_t Bsm, int t, int tid) {
    const int pc = t / 12, s = t % 12;
    const char* src0 = reinterpret_cast<const char*>((s < 8) ? g_bh : g_bl);
    const int kb = (s < 8) ? (s & 3) : (s - 8);
    const uint32_t dst = Bsm + (uint32_t)(t % 3) * 16384u;
    #pragma unroll
    for (int i = 0; i < 4; ++i) {
        int u = tid + (i << 8);          // 0..1023 16B units
        int r = u >> 3, c = u & 7;
        uint32_t o = (uint32_t)(r << 7) + (uint32_t)(c << 4);
        const char* src = src0 + (size_t)(pc * 128 + r) * 512 + kb * 128 + (c << 4);
        cpa16(dst + (o ^ ((o >> 3) & 0x70)), src);
    }
}

// ---------------------------------------------------------------------------
// Main: 512 blocks x 128 pixels. A (128x512 fp16) staged once (128KB smem);
// 48 B slices (16KB) 3-stage pipelined. mma m16n8k16 fp32 acc, top-2 epilogue.
// ---------------------------------------------------------------------------
__global__ __launch_bounds__(256, 1)
void protomatch_mma(float* __restrict__ out, long long out_size)
{
    extern __shared__ char dsm[];
    const uint32_t dynb = smem_u32(dsm);
    const uint32_t base = (dynb + 1023u) & ~1023u;
    char* base_g = dsm + (base - dynb);
    const uint32_t Asm = base;            // 131072 bytes (8 chunks x 16KB)
    const uint32_t Bsm = base + 131072u;  // 49152 bytes (3 bufs x 16KB)

    const int tid = threadIdx.x, lane = tid & 31, wid = tid >> 5;
    const int warp_m = wid & 3, warp_n = wid >> 2;
    const int m0 = blockIdx.x << 7;

    // ---- stage A (128 rows x 512 fp16) + B slice 0 (group 0) ----
    const char* Ag = reinterpret_cast<const char*>(g_a);
    #pragma unroll
    for (int i = 0; i < 32; ++i) {
        int u = tid + (i << 8);          // 0..8191 16B units
        int s = u >> 10;                 // chunk 0..7
        int r = (u >> 3) & 127;          // row 0..127
        int c = u & 7;                   // 16B col 0..7
        uint32_t o = (uint32_t)(r << 7) + (uint32_t)(c << 4);
        cpa16(Asm + (s << 14) + (o ^ ((o >> 3) & 0x70)),
              Ag + (size_t)(m0 + r) * 1024 + (s << 7) + (c << 4));
    }
    load_bslice(Bsm, 0, tid);
    asm volatile("cp.async.commit_group;");
    load_bslice(Bsm, 1, tid);
    asm volatile("cp.async.commit_group;");

    // per-lane ldmatrix address components
    uint32_t aoff[2], aswz[2];
    #pragma unroll
    for (int mt = 0; mt < 2; ++mt) {
        int rowA = warp_m * 32 + mt * 16 + (lane & 15);
        aoff[mt] = (uint32_t)rowA << 7;
        aswz[mt] = (uint32_t)(rowA & 7);
    }
    const uint32_t alc = (uint32_t)(lane >> 4);        // k-half select for A

    uint32_t boff[4], bswz[4];
    #pragma unroll
    for (int nt2 = 0; nt2 < 4; ++nt2) {
        int rowB = warp_n * 64 + nt2 * 16 + ((lane >> 4) << 3) + (lane & 7);
        boff[nt2] = (uint32_t)rowB << 7;
        bswz[nt2] = (uint32_t)(rowB & 7);
    }
    const uint32_t blc = (uint32_t)((lane >> 3) & 1);  // k-half select for B

    float acc[2][8][4];
    float t1v[4], t2v[4];
    int   t1i[4];
    #pragma unroll
    for (int s = 0; s < 4; ++s) { t1v[s] = -CUDART_INF_F; t2v[s] = -CUDART_INF_F; t1i[s] = 0; }

    for (int t = 0; t < 48; ++t) {
        const int pc = t / 12, s = t % 12;
        if (s == 0) {
            #pragma unroll
            for (int i = 0; i < 2; ++i)
                #pragma unroll
                for (int j = 0; j < 8; ++j)
                    #pragma unroll
                    for (int q = 0; q < 4; ++q) acc[i][j][q] = 0.f;
        }
        // pipeline: wait(tile t ready) -> sync -> issue copy t+2 -> compute
        if (t < 47) asm volatile("cp.async.wait_group 1;");
        else        asm volatile("cp.async.wait_group 0;");
        __syncthreads();
        if (t + 2 < 48) {
            load_bslice(Bsm, t + 2, tid);
            asm volatile("cp.async.commit_group;");
        }

        const int a_ch = (s < 8) ? s : (s - 8);
        const uint32_t Ab = Asm + ((uint32_t)a_ch << 14);
        const uint32_t Bb = Bsm + (uint32_t)(t % 3) * 16384u;

        #pragma unroll
        for (int k16 = 0; k16 < 4; ++k16) {
            uint32_t ra[2][4];
            #pragma unroll
            for (int mt = 0; mt < 2; ++mt) {
                uint32_t c16 = (uint32_t)(k16 << 1) + alc;
                LDSM_X4(ra[mt][0], ra[mt][1], ra[mt][2], ra[mt][3],
                        Ab + aoff[mt] + ((c16 ^ aswz[mt]) << 4));
            }
            #pragma unroll
            for (int nt2 = 0; nt2 < 4; ++nt2) {
                uint32_t c16 = (uint32_t)(k16 << 1) + blc;
                uint32_t rb[4];
                LDSM_X4(rb[0], rb[1], rb[2], rb[3],
                        Bb + boff[nt2] + ((c16 ^ bswz[nt2]) << 4));
                MMA16816(acc[0][2*nt2+0], ra[0], (rb + 0));
                MMA16816(acc[1][2*nt2+0], ra[1], (rb + 0));
                MMA16816(acc[0][2*nt2+1], ra[0], (rb + 2));
                MMA16816(acc[1][2*nt2+1], ra[1], (rb + 2));
            }
        }

        if (s == 11) {     // fold chunk into running top-2
            #pragma unroll
            for (int mt = 0; mt < 2; ++mt)
                #pragma unroll
                for (int rh = 0; rh < 2; ++rh) {
                    int sl = mt * 2 + rh;
                    #pragma unroll
                    for (int nt = 0; nt < 8; ++nt)
                        #pragma unroll
                        for (int e = 0; e < 2; ++e) {
                            float v = acc[mt][nt][rh * 2 + e];
                            int col = (pc << 7) + (warp_n << 6) + (nt << 3)
                                    + ((lane & 3) << 1) + e;
                            if (v > t1v[sl]) { t2v[sl] = t1v[sl]; t1v[sl] = v; t1i[sl] = col; }
                            else if (v > t2v[sl]) t2v[sl] = v;
                        }
                }
        }
    }
    __syncthreads();

    // ---- cross-lane/warp reduction via smem (reuse A region) ----
    float* sv1 = reinterpret_cast<float*>(base_g);
    int*   si1 = reinterpret_cast<int*>(base_g + 4096);
    float* sv2 = reinterpret_cast<float*>(base_g + 8192);
    #pragma unroll
    for (int mt = 0; mt < 2; ++mt)
        #pragma unroll
        for (int rh = 0; rh < 2; ++rh) {
            int sl = mt * 2 + rh;
            int row = warp_m * 32 + mt * 16 + rh * 8 + (lane >> 2);
            int cand = (warp_n << 2) + (lane & 3);
            sv1[row * 8 + cand] = t1v[sl];
            si1[row * 8 + cand] = t1i[sl];
            sv2[row * 8 + cand] = t2v[sl];
        }
    __syncthreads();

    if (tid < 128) {
        float v1 = -CUDART_INF_F, v2 = -CUDART_INF_F;
        int i1 = 0x7fffffff;
        #pragma unroll
        for (int c = 0; c < 8; ++c) {
            float cv1 = sv1[tid * 8 + c], cv2 = sv2[tid * 8 + c];
            int   ci1 = si1[tid * 8 + c];
            if (cv1 > v1 || (cv1 == v1 && ci1 < i1)) {
                v2 = fmaxf(v1, cv2); v1 = cv1; i1 = ci1;
            } else {
                v2 = fmaxf(v2, cv1);
            }
        }
        const int m = m0 + tid;
        g_idx[m] = i1;
        if (out_size > 16777216LL) out[16777216 + m] = (float)i1;
        if (v1 - v2 < 1e-4f) {
            int pos = atomicAdd(&g_nfix, 1);
            g_fixlist[pos] = m;
        }
    }
}

// ---------------------------------------------------------------------------
// Fixup: exact fp32 argmax for flagged pixels, 8 entries batched per block
// ---------------------------------------------------------------------------
__global__ __launch_bounds__(256)
void fixup_kernel(const float* __restrict__ x, float* __restrict__ out,
                  long long out_size)
{
    __shared__ __align__(16) float xs[8][260];
    __shared__ float rbv[8][8];
    __shared__ int   rbi[8][8];
    const int tid = threadIdx.x, lane = tid & 31, wid = tid >> 5;
    const int nfix = g_nfix;

    for (int g0 = blockIdx.x * 8; g0 < nfix; g0 += gridDim.x * 8) {
        const int ne = min(8, nfix - g0);
        for (int i = tid; i < (ne << 8); i += 256) {
            int e = i >> 8, c = i & 255;
            int m = g_fixlist[g0 + e];
            xs[e][c] = x[(m >> 10) * 262144 + c * 1024 + (m & 1023)];
        }
        __syncthreads();

        float bv[8]; int bi[8];
        #pragma unroll
        for (int e = 0; e < 8; ++e) { bv[e] = -CUDART_INF_F; bi[e] = 0; }

        #pragma unroll
        for (int h = 0; h < 2; ++h) {
            const int p = tid + (h << 8);
            const float4* pr = reinterpret_cast<const float4*>(g_pnf + (p << 8));
            float acc[8];
            #pragma unroll
            for (int e = 0; e < 8; ++e) acc[e] = 0.f;
            #pragma unroll 4
            for (int c4 = 0; c4 < 64; ++c4) {
                float4 pv = pr[c4];
                #pragma unroll
                for (int e = 0; e < 8; ++e) {
                    float4 xv = reinterpret_cast<const float4*>(xs[e])[c4];
                    acc[e] = fmaf(pv.x, xv.x, acc[e]);
                    acc[e] = fmaf(pv.y, xv.y, acc[e]);
                    acc[e] = fmaf(pv.z, xv.z, acc[e]);
                    acc[e] = fmaf(pv.w, xv.w, acc[e]);
                }
            }
            #pragma unroll
            for (int e = 0; e < 8; ++e)
                if (acc[e] > bv[e]) { bv[e] = acc[e]; bi[e] = p; }  // ascending p
        }

        #pragma unroll
        for (int e = 0; e < 8; ++e) {
            float v = bv[e]; int ix = bi[e];
            #pragma unroll
            for (int s = 16; s >= 1; s >>= 1) {
                float ov = __shfl_xor_sync(0xffffffffu, v, s);
                int   oi = __shfl_xor_sync(0xffffffffu, ix, s);
                if (ov > v || (ov == v && oi < ix)) { v = ov; ix = oi; }
            }
            if (lane == 0) { rbv[e][wid] = v; rbi[e][wid] = ix; }
        }
        __syncthreads();

        if (tid < ne) {
            float fv = rbv[tid][0]; int fi = rbi[tid][0];
            #pragma unroll
            for (int w = 1; w < 8; ++w)
                if (rbv[tid][w] > fv || (rbv[tid][w] == fv && rbi[tid][w] < fi)) {
                    fv = rbv[tid][w]; fi = rbi[tid][w];
                }
            const int m = g_fixlist[g0 + tid];
            g_idx[m] = fi;
            if (out_size > 16777216LL) out[16777216 + m] = (float)fi;
        }
        __syncthreads();
    }
}

// ---------------------------------------------------------------------------
// Gather: recon[b,c,h,w] = proto[idx[pixel]][c], coalesced
// ---------------------------------------------------------------------------
__global__ __launch_bounds__(256)
void gather_kernel(const float* __restrict__ proto, float* __restrict__ out)
{
    __shared__ int sIdx[128];
    const int tid = threadIdx.x;
    const int m0 = blockIdx.x << 7, b = m0 >> 10, n0 = m0 & 1023;
    if (tid < 128) sIdx[tid] = g_idx[m0 + tid];
    __syncthreads();
    const int n4 = tid & 31, co = tid >> 5;
    const float* r0 = proto + (sIdx[(n4 << 2) + 0] << 8);
    const float* r1 = proto + (sIdx[(n4 << 2) + 1] << 8);
    const float* r2 = proto + (sIdx[(n4 << 2) + 2] << 8);
    const float* r3 = proto + (sIdx[(n4 << 2) + 3] << 8);
    float4* Og = reinterpret_cast<float4*>(out) + (b * 65536 + (n0 >> 2) + n4);
    #pragma unroll 4
    for (int c = co; c < 256; c += 8)
        Og[c * 256] = make_float4(r0[c], r1[c], r2[c], r3[c]);
}

// ---------------------------------------------------------------------------
extern "C" void kernel_launch(void* const* d_in, const int* in_sizes, int n_in,
                              void* d_out, int out_size)
{
    const float* x     = (const float*)d_in[0];
    const float* proto = (const float*)d_in[1];
    if (n_in >= 2 && in_sizes[0] == 512 * 256 && in_sizes[1] != 512 * 256) {
        proto = (const float*)d_in[0];
        x     = (const float*)d_in[1];
    }
    float* out = (float*)d_out;

    proto_prep_kernel<<<512, 256>>>(proto);
    xsplit_kernel<<<dim3(8, 32, 64), 256>>>(x);

    cudaFuncSetAttribute(protomatch_mma,
                         cudaFuncAttributeMaxDynamicSharedMemorySize, 181248);
    protomatch_mma<<<512, 256, 181248>>>(out, (long long)out_size);

    fixup_kernel<<<128, 256>>>(x, out, (long long)out_size);
    gather_kernel<<<512, 256>>>(proto, out);
}

// round 7
// speedup vs baseline: 1.6029x; 1.0030x over previous
#include <cuda_runtime.h>
#include <cuda_fp16.h>
#include <cstdint>
#include <math_constants.h>

// ---------------------------------------------------------------------------
// Device scratch (static: allocation-free)
// ---------------------------------------------------------------------------
__device__ __half g_a [65536 * 512];   // A pixel-major [m][ cols 0-255 = xh, 256-511 = xl ]
__device__ __half g_bh[512 * 256];     // normalized proto hi [p][c]
__device__ __half g_bl[512 * 256];     // normalized proto lo [p][c]
__device__ float  g_pnf[512 * 256];    // normalized protos fp32 (for fixup)
__device__ int    g_idx[65536];        // per-pixel argmax
__device__ int    g_fixlist[65536];
__device__ int    g_nfix;

__device__ __forceinline__ uint32_t smem_u32(const void* p) {
    uint32_t a;
    asm("{ .reg .u64 t; cvta.to.shared.u64 t, %1; cvt.u32.u64 %0, t; }"
        : "=r"(a) : "l"(p));
    return a;
}
__device__ __forceinline__ void cpa16(uint32_t dst, const void* src) {
    asm volatile("cp.async.cg.shared.global [%0], [%1], 16;"
                 :: "r"(dst), "l"(src));
}
#define LDSM_X4(r0,r1,r2,r3,addr) \
    asm volatile("ldmatrix.sync.aligned.m8n8.x4.shared.b16 {%0,%1,%2,%3}, [%4];" \
        : "=r"(r0),"=r"(r1),"=r"(r2),"=r"(r3) : "r"(addr))
#define MMA16816(d,a,b) \
    asm volatile("mma.sync.aligned.m16n8k16.row.col.f32.f16.f16.f32 " \
        "{%0,%1,%2,%3},{%4,%5,%6,%7},{%8,%9},{%0,%1,%2,%3};" \
        : "+f"(d[0]),"+f"(d[1]),"+f"(d[2]),"+f"(d[3]) \
        : "r"(a[0]),"r"(a[1]),"r"(a[2]),"r"(a[3]),"r"(b[0]),"r"(b[1]))

// slice schedule rotation: block bid at linear step t works on
//   pc = (t/12 + bid) & 3,  s = (t%12 + bid) % 12
__device__ __forceinline__ void slice_coords(int t, int bid, int& pc, int& s) {
    pc = ((t / 12) + bid) & 3;
    s  = ((t % 12) + bid) % 12;
}

// ---------------------------------------------------------------------------
// Prep 1: normalize protos -> fp16 hi/lo banks + fp32 copy; reset fix counter
// ---------------------------------------------------------------------------
__global__ void proto_prep_kernel(const float* __restrict__ proto) {
    __shared__ float sred[8];
    const int p = blockIdx.x, c = threadIdx.x;
    float v = proto[(p << 8) + c];
    float ss = v * v;
    #pragma unroll
    for (int s = 16; s >= 1; s >>= 1) ss += __shfl_xor_sync(0xffffffffu, ss, s);
    if ((c & 31) == 0) sred[c >> 5] = ss;
    __syncthreads();
    float tot = 0.f;
    #pragma unroll
    for (int w = 0; w < 8; ++w) tot += sred[w];
    const float pn = v / fmaxf(sqrtf(tot), 1e-12f);
    g_pnf[(p << 8) + c] = pn;
    __half bh = __float2half(pn);
    g_bh[(p << 8) + c] = bh;
    g_bl[(p << 8) + c] = __float2half(pn - __half2float(bh));
    if (p == 0 && c == 0) g_nfix = 0;
}

// ---------------------------------------------------------------------------
// Prep 2: transpose x [b][c][m] -> A [m][xh(0..255) | xl(256..511)] fp16
// ---------------------------------------------------------------------------
__global__ void xsplit_kernel(const float* __restrict__ x) {
    __shared__ float t[32][33];
    const int b = blockIdx.z, c0 = blockIdx.x << 5, m0 = blockIdx.y << 5;
    const int tx = threadIdx.x & 31, ty = threadIdx.x >> 5;
    #pragma unroll
    for (int i = 0; i < 4; ++i) {
        int c = ty + (i << 3);
        t[c][tx] = x[b * 262144 + (c0 + c) * 1024 + m0 + tx];
    }
    __syncthreads();
    #pragma unroll
    for (int i = 0; i < 4; ++i) {
        int m = ty + (i << 3);
        float v = t[tx][m];
        __half h = __float2half(v);
        __half l = __float2half(v - __half2float(h));
        size_t row = (size_t)(b * 1024 + m0 + m) << 9;
        g_a[row + c0 + tx]       = h;
        g_a[row + 256 + c0 + tx] = l;
    }
}

// ---------------------------------------------------------------------------
// B slice loader: 128 protos x 64 k fp16 = 16KB into buf (t%3), SW128 swizzle
// slice s: 0-7 -> bh k-chunk (s&3)... mapping: s<8 -> bh chunk s&3? NO:
// s 0-7 -> bh k-chunk (s in 0..7 maps to a_ch s, k-chunk s&3 of 4 chunks of 64)
// careful: bh has 256 ch = 4 chunks of 64. slices 0-7 pair with A chunks 0-7
// (xh chunks 0-3 then 4-7?) -- A chunk a covers channels a*32... A is 512 cols
// of 64-col chunks: chunks 0-3 = xh(256), 4-7 = xl(256).
// Slices 0-7: bh chunks 0-3 against A chunks 0-3 (hh) AND bh chunks 0-3 against
// A chunks 4-7 (lh): s pairs (A chunk s, bh chunk s&3).
// Slices 8-11: bl chunk (s-8) against A chunk (s-8) (hl).
// ---------------------------------------------------------------------------
__device__ __forceinline__ void load_bslice(uint32_t Bsm, int t, int tid, int bid) {
    int pc, s;
    slice_coords(t, bid, pc, s);
    const char* src0 = reinterpret_cast<const char*>((s < 8) ? g_bh : g_bl);
    const int kb = (s < 8) ? (s & 3) : (s - 8);
    const uint32_t dst = Bsm + (uint32_t)(t % 3) * 16384u;
    #pragma unroll
    for (int i = 0; i < 4; ++i) {
        int u = tid + (i << 8);          // 0..1023 16B units
        int r = u >> 3, c = u & 7;
        uint32_t o = (uint32_t)(r << 7) + (uint32_t)(c << 4);
        const char* src = src0 + (size_t)(pc * 128 + r) * 512 + kb * 128 + (c << 4);
        cpa16(dst + (o ^ ((o >> 3) & 0x70)), src);
    }
}

// ---------------------------------------------------------------------------
// Main: 512 blocks x 128 pixels. A (128x512 fp16) staged once (128KB smem);
// 48 B slices (16KB) 3-stage pipelined, per-block rotated schedule.
// mma m16n8k16 fp32 acc, top-2 epilogue.
// ---------------------------------------------------------------------------
__global__ __launch_bounds__(256, 1)
void protomatch_mma(float* __restrict__ out, long long out_size)
{
    extern __shared__ char dsm[];
    const uint32_t dynb = smem_u32(dsm);
    const uint32_t base = (dynb + 1023u) & ~1023u;
    char* base_g = dsm + (base - dynb);
    const uint32_t Asm = base;            // 131072 bytes (8 chunks x 16KB)
    const uint32_t Bsm = base + 131072u;  // 49152 bytes (3 bufs x 16KB)

    const int tid = threadIdx.x, lane = tid & 31, wid = tid >> 5;
    const int warp_m = wid & 3, warp_n = wid >> 2;
    const int bid = blockIdx.x;
    const int m0 = bid << 7;

    // ---- stage A (128 rows x 512 fp16) + first two B slices ----
    const char* Ag = reinterpret_cast<const char*>(g_a);
    #pragma unroll
    for (int i = 0; i < 32; ++i) {
        int u = tid + (i << 8);          // 0..8191 16B units
        int s = u >> 10;                 // chunk 0..7
        int r = (u >> 3) & 127;          // row 0..127
        int c = u & 7;                   // 16B col 0..7
        uint32_t o = (uint32_t)(r << 7) + (uint32_t)(c << 4);
        cpa16(Asm + (s << 14) + (o ^ ((o >> 3) & 0x70)),
              Ag + (size_t)(m0 + r) * 1024 + (s << 7) + (c << 4));
    }
    load_bslice(Bsm, 0, tid, bid);
    asm volatile("cp.async.commit_group;");
    load_bslice(Bsm, 1, tid, bid);
    asm volatile("cp.async.commit_group;");

    // per-lane ldmatrix address components
    uint32_t aoff[2], aswz[2];
    #pragma unroll
    for (int mt = 0; mt < 2; ++mt) {
        int rowA = warp_m * 32 + mt * 16 + (lane & 15);
        aoff[mt] = (uint32_t)rowA << 7;
        aswz[mt] = (uint32_t)(rowA & 7);
    }
    const uint32_t alc = (uint32_t)(lane >> 4);        // k-half select for A

    uint32_t boff[4], bswz[4];
    #pragma unroll
    for (int nt2 = 0; nt2 < 4; ++nt2) {
        int rowB = warp_n * 64 + nt2 * 16 + ((lane >> 4) << 3) + (lane & 7);
        boff[nt2] = (uint32_t)rowB << 7;
        bswz[nt2] = (uint32_t)(rowB & 7);
    }
    const uint32_t blc = (uint32_t)((lane >> 3) & 1);  // k-half select for B

    float acc[2][8][4];
    float t1v[4], t2v[4];
    int   t1i[4];
    #pragma unroll
    for (int s = 0; s < 4; ++s) { t1v[s] = -CUDART_INF_F; t2v[s] = -CUDART_INF_F; t1i[s] = 0; }

    for (int t = 0; t < 48; ++t) {
        const int sx = t % 12;
        int pc, s;
        slice_coords(t, bid, pc, s);
        if (sx == 0) {
            #pragma unroll
            for (int i = 0; i < 2; ++i)
                #pragma unroll
                for (int j = 0; j < 8; ++j)
                    #pragma unroll
                    for (int q = 0; q < 4; ++q) acc[i][j][q] = 0.f;
        }
        // pipeline: wait(tile t ready) -> sync -> issue copy t+2 -> compute
        if (t < 47) asm volatile("cp.async.wait_group 1;");
        else        asm volatile("cp.async.wait_group 0;");
        __syncthreads();
        if (t + 2 < 48) {
            load_bslice(Bsm, t + 2, tid, bid);
            asm volatile("cp.async.commit_group;");
        }

        const int a_ch = (s < 8) ? s : (s - 8);
        const uint32_t Ab = Asm + ((uint32_t)a_ch << 14);
        const uint32_t Bb = Bsm + (uint32_t)(t % 3) * 16384u;

        #pragma unroll
        for (int k16 = 0; k16 < 4; ++k16) {
            uint32_t ra[2][4];
            #pragma unroll
            for (int mt = 0; mt < 2; ++mt) {
                uint32_t c16 = (uint32_t)(k16 << 1) + alc;
                LDSM_X4(ra[mt][0], ra[mt][1], ra[mt][2], ra[mt][3],
                        Ab + aoff[mt] + ((c16 ^ aswz[mt]) << 4));
            }
            #pragma unroll
            for (int nt2 = 0; nt2 < 4; ++nt2) {
                uint32_t c16 = (uint32_t)(k16 << 1) + blc;
                uint32_t rb[4];
                LDSM_X4(rb[0], rb[1], rb[2], rb[3],
                        Bb + boff[nt2] + ((c16 ^ bswz[nt2]) << 4));
                MMA16816(acc[0][2*nt2+0], ra[0], (rb + 0));
                MMA16816(acc[1][2*nt2+0], ra[1], (rb + 0));
                MMA16816(acc[0][2*nt2+1], ra[0], (rb + 2));
                MMA16816(acc[1][2*nt2+1], ra[1], (rb + 2));
            }
        }

        if (sx == 11) {    // fold chunk pc into running top-2
            #pragma unroll
            for (int mt = 0; mt < 2; ++mt)
                #pragma unroll
                for (int rh = 0; rh < 2; ++rh) {
                    int sl = mt * 2 + rh;
                    #pragma unroll
                    for (int nt = 0; nt < 8; ++nt)
                        #pragma unroll
                        for (int e = 0; e < 2; ++e) {
                            float v = acc[mt][nt][rh * 2 + e];
                            int col = (pc << 7) + (warp_n << 6) + (nt << 3)
                                    + ((lane & 3) << 1) + e;
                            if (v > t1v[sl]) { t2v[sl] = t1v[sl]; t1v[sl] = v; t1i[sl] = col; }
                            else if (v > t2v[sl]) t2v[sl] = v;
                        }
                }
        }
    }
    __syncthreads();

    // ---- cross-lane/warp reduction via smem (reuse A region) ----
    float* sv1 = reinterpret_cast<float*>(base_g);
    int*   si1 = reinterpret_cast<int*>(base_g + 4096);
    float* sv2 = reinterpret_cast<float*>(base_g + 8192);
    #pragma unroll
    for (int mt = 0; mt < 2; ++mt)
        #pragma unroll
        for (int rh = 0; rh < 2; ++rh) {
            int sl = mt * 2 + rh;
            int row = warp_m * 32 + mt * 16 + rh * 8 + (lane >> 2);
            int cand = (warp_n << 2) + (lane & 3);
            sv1[row * 8 + cand] = t1v[sl];
            si1[row * 8 + cand] = t1i[sl];
            sv2[row * 8 + cand] = t2v[sl];
        }
    __syncthreads();

    if (tid < 128) {
        float v1 = -CUDART_INF_F, v2 = -CUDART_INF_F;
        int i1 = 0x7fffffff;
        #pragma unroll
        for (int c = 0; c < 8; ++c) {
            float cv1 = sv1[tid * 8 + c], cv2 = sv2[tid * 8 + c];
            int   ci1 = si1[tid * 8 + c];
            if (cv1 > v1 || (cv1 == v1 && ci1 < i1)) {
                v2 = fmaxf(v1, cv2); v1 = cv1; i1 = ci1;
            } else {
                v2 = fmaxf(v2, cv1);
            }
        }
        const int m = m0 + tid;
        g_idx[m] = i1;
        if (out_size > 16777216LL) out[16777216 + m] = (float)i1;
        if (v1 - v2 < 1e-4f) {
            int pos = atomicAdd(&g_nfix, 1);
            g_fixlist[pos] = m;
        }
    }
}

// ---------------------------------------------------------------------------
// Fixup: exact fp32 argmax for flagged pixels, 8 entries batched per block
// ---------------------------------------------------------------------------
__global__ __launch_bounds__(256)
void fixup_kernel(const float* __restrict__ x, float* __restrict__ out,
                  long long out_size)
{
    __shared__ __align__(16) float xs[8][260];
    __shared__ float rbv[8][8];
    __shared__ int   rbi[8][8];
    const int tid = threadIdx.x, lane = tid & 31, wid = tid >> 5;
    const int nfix = g_nfix;

    for (int g0 = blockIdx.x * 8; g0 < nfix; g0 += gridDim.x * 8) {
        const int ne = min(8, nfix - g0);
        for (int i = tid; i < (ne << 8); i += 256) {
            int e = i >> 8, c = i & 255;
            int m = g_fixlist[g0 + e];
            xs[e][c] = x[(m >> 10) * 262144 + c * 1024 + (m & 1023)];
        }
        __syncthreads();

        float bv[8]; int bi[8];
        #pragma unroll
        for (int e = 0; e < 8; ++e) { bv[e] = -CUDART_INF_F; bi[e] = 0; }

        #pragma unroll
        for (int h = 0; h < 2; ++h) {
            const int p = tid + (h << 8);
            const float4* pr = reinterpret_cast<const float4*>(g_pnf + (p << 8));
            float acc[8];
            #pragma unroll
            for (int e = 0; e < 8; ++e) acc[e] = 0.f;
            #pragma unroll 4
            for (int c4 = 0; c4 < 64; ++c4) {
                float4 pv = pr[c4];
                #pragma unroll
                for (int e = 0; e < 8; ++e) {
                    float4 xv = reinterpret_cast<const float4*>(xs[e])[c4];
                    acc[e] = fmaf(pv.x, xv.x, acc[e]);
                    acc[e] = fmaf(pv.y, xv.y, acc[e]);
                    acc[e] = fmaf(pv.z, xv.z, acc[e]);
                    acc[e] = fmaf(pv.w, xv.w, acc[e]);
                }
            }
            #pragma unroll
            for (int e = 0; e < 8; ++e)
                if (acc[e] > bv[e]) { bv[e] = acc[e]; bi[e] = p; }  // ascending p
        }

        #pragma unroll
        for (int e = 0; e < 8; ++e) {
            float v = bv[e]; int ix = bi[e];
            #pragma unroll
            for (int s = 16; s >= 1; s >>= 1) {
                float ov = __shfl_xor_sync(0xffffffffu, v, s);
                int   oi = __shfl_xor_sync(0xffffffffu, ix, s);
                if (ov > v || (ov == v && oi < ix)) { v = ov; ix = oi; }
            }
            if (lane == 0) { rbv[e][wid] = v; rbi[e][wid] = ix; }
        }
        __syncthreads();

        if (tid < ne) {
            float fv = rbv[tid][0]; int fi = rbi[tid][0];
            #pragma unroll
            for (int w = 1; w < 8; ++w)
                if (rbv[tid][w] > fv || (rbv[tid][w] == fv && rbi[tid][w] < fi)) {
                    fv = rbv[tid][w]; fi = rbi[tid][w];
                }
            const int m = g_fixlist[g0 + tid];
            g_idx[m] = fi;
            if (out_size > 16777216LL) out[16777216 + m] = (float)fi;
        }
        __syncthreads();
    }
}

// ---------------------------------------------------------------------------
// Gather: recon[b,c,h,w] = proto[idx[pixel]][c], coalesced
// ---------------------------------------------------------------------------
__global__ __launch_bounds__(256)
void gather_kernel(const float* __restrict__ proto, float* __restrict__ out)
{
    __shared__ int sIdx[128];
    const int tid = threadIdx.x;
    const int m0 = blockIdx.x << 7, b = m0 >> 10, n0 = m0 & 1023;
    if (tid < 128) sIdx[tid] = g_idx[m0 + tid];
    __syncthreads();
    const int n4 = tid & 31, co = tid >> 5;
    const float* r0 = proto + (sIdx[(n4 << 2) + 0] << 8);
    const float* r1 = proto + (sIdx[(n4 << 2) + 1] << 8);
    const float* r2 = proto + (sIdx[(n4 << 2) + 2] << 8);
    const float* r3 = proto + (sIdx[(n4 << 2) + 3] << 8);
    float4* Og = reinterpret_cast<float4*>(out) + (b * 65536 + (n0 >> 2) + n4);
    #pragma unroll 4
    for (int c = co; c < 256; c += 8)
        Og[c * 256] = make_float4(r0[c], r1[c], r2[c], r3[c]);
}

// ---------------------------------------------------------------------------
extern "C" void kernel_launch(void* const* d_in, const int* in_sizes, int n_in,
                              void* d_out, int out_size)
{
    const float* x     = (const float*)d_in[0];
    const float* proto = (const float*)d_in[1];
    if (n_in >= 2 && in_sizes[0] == 512 * 256 && in_sizes[1] != 512 * 256) {
        proto = (const float*)d_in[0];
        x     = (const float*)d_in[1];
    }
    float* out = (float*)d_out;

    proto_prep_kernel<<<512, 256>>>(proto);
    xsplit_kernel<<<dim3(8, 32, 64), 256>>>(x);

    cudaFuncSetAttribute(protomatch_mma,
                         cudaFuncAttributeMaxDynamicSharedMemorySize, 181248);
    protomatch_mma<<<512, 256, 181248>>>(out, (long long)out_size);

    fixup_kernel<<<128, 256>>>(x, out, (long long)out_size);
    gather_kernel<<<512, 256>>>(proto, out);
}

// round 8
// speedup vs baseline: 1.6441x; 1.0257x over previous
#include <cuda_runtime.h>
#include <cuda_fp16.h>
#include <cstdint>
#include <math_constants.h>

// ---------------------------------------------------------------------------
// Device scratch (static: allocation-free)
// ---------------------------------------------------------------------------
__device__ __half g_a [65536 * 512];   // A pixel-major [m][ cols 0-255 = xh, 256-511 = xl ]
__device__ __half g_bh[512 * 256];     // normalized proto hi [p][c]
__device__ __half g_bl[512 * 256];     // normalized proto lo [p][c]
__device__ float  g_pnf[512 * 256];    // normalized protos fp32 (for fixup)
__device__ int    g_idx[65536];        // per-pixel argmax
__device__ int    g_fixlist[65536];
__device__ int    g_nfix;

__device__ __forceinline__ uint32_t smem_u32(const void* p) {
    uint32_t a;
    asm("{ .reg .u64 t; cvta.to.shared.u64 t, %1; cvt.u32.u64 %0, t; }"
        : "=r"(a) : "l"(p));
    return a;
}
__device__ __forceinline__ void cpa16(uint32_t dst, const void* src) {
    asm volatile("cp.async.cg.shared.global [%0], [%1], 16;"
                 :: "r"(dst), "l"(src));
}
#define LDSM_X4(r0,r1,r2,r3,addr) \
    asm volatile("ldmatrix.sync.aligned.m8n8.x4.shared.b16 {%0,%1,%2,%3}, [%4];" \
        : "=r"(r0),"=r"(r1),"=r"(r2),"=r"(r3) : "r"(addr))
#define MMA16816(d,a,b) \
    asm volatile("mma.sync.aligned.m16n8k16.row.col.f32.f16.f16.f32 " \
        "{%0,%1,%2,%3},{%4,%5,%6,%7},{%8,%9},{%0,%1,%2,%3};" \
        : "+f"(d[0]),"+f"(d[1]),"+f"(d[2]),"+f"(d[3]) \
        : "r"(a[0]),"r"(a[1]),"r"(a[2]),"r"(a[3]),"r"(b[0]),"r"(b[1]))

// ---------------------------------------------------------------------------
// Prep 1: normalize protos -> fp16 hi/lo banks + fp32 copy; reset fix counter
// ---------------------------------------------------------------------------
__global__ void proto_prep_kernel(const float* __restrict__ proto) {
    __shared__ float sred[8];
    const int p = blockIdx.x, c = threadIdx.x;
    float v = proto[(p << 8) + c];
    float ss = v * v;
    #pragma unroll
    for (int s = 16; s >= 1; s >>= 1) ss += __shfl_xor_sync(0xffffffffu, ss, s);
    if ((c & 31) == 0) sred[c >> 5] = ss;
    __syncthreads();
    float tot = 0.f;
    #pragma unroll
    for (int w = 0; w < 8; ++w) tot += sred[w];
    const float pn = v / fmaxf(sqrtf(tot), 1e-12f);
    g_pnf[(p << 8) + c] = pn;
    __half bh = __float2half(pn);
    g_bh[(p << 8) + c] = bh;
    g_bl[(p << 8) + c] = __float2half(pn - __half2float(bh));
    if (p == 0 && c == 0) g_nfix = 0;
}

// ---------------------------------------------------------------------------
// Prep 2: transpose x [b][c][m] -> A [m][xh(0..255) | xl(256..511)] fp16
// ---------------------------------------------------------------------------
__global__ void xsplit_kernel(const float* __restrict__ x) {
    __shared__ float t[32][33];
    const int b = blockIdx.z, c0 = blockIdx.x << 5, m0 = blockIdx.y << 5;
    const int tx = threadIdx.x & 31, ty = threadIdx.x >> 5;
    #pragma unroll
    for (int i = 0; i < 4; ++i) {
        int c = ty + (i << 3);
        t[c][tx] = x[b * 262144 + (c0 + c) * 1024 + m0 + tx];
    }
    __syncthreads();
    #pragma unroll
    for (int i = 0; i < 4; ++i) {
        int m = ty + (i << 3);
        float v = t[tx][m];
        __half h = __float2half(v);
        __half l = __float2half(v - __half2float(h));
        size_t row = (size_t)(b * 1024 + m0 + m) << 9;
        g_a[row + c0 + tx]       = h;
        g_a[row + 256 + c0 + tx] = l;
    }
}

// ---------------------------------------------------------------------------
// B slice loader (512 threads): 128 protos x 64 k fp16 = 16KB into buf (t%3).
// Slice s of proto-chunk pc = t/12: s 0-7 -> bh k-chunk s&3 (vs A chunk s),
// s 8-11 -> bl k-chunk s-8 (vs A chunk s-8).
// ---------------------------------------------------------------------------
__device__ __forceinline__ void load_bslice(uint32_t Bsm, int t, int tid) {
    const int pc = t / 12, s = t % 12;
    const char* src0 = reinterpret_cast<const char*>((s < 8) ? g_bh : g_bl);
    const int kb = (s < 8) ? (s & 3) : (s - 8);
    const uint32_t dst = Bsm + (uint32_t)(t % 3) * 16384u;
    #pragma unroll
    for (int i = 0; i < 2; ++i) {
        int u = tid + (i << 9);          // 0..1023 16B units
        int r = u >> 3, c = u & 7;
        uint32_t o = (uint32_t)(r << 7) + (uint32_t)(c << 4);
        const char* src = src0 + (size_t)(pc * 128 + r) * 512 + kb * 128 + (c << 4);
        cpa16(dst + (o ^ ((o >> 3) & 0x70)), src);
    }
}

// ---------------------------------------------------------------------------
// Main: 512 blocks x 128 pixels, 512 threads (16 warps, 4/SMSP).
// A (128x512 fp16) staged once (128KB smem); 48 B slices (16KB) 3-stage
// pipelined. Warp grid 4m x 4n, 32x32 tile/warp. fp32 acc, top-2 epilogue.
// ---------------------------------------------------------------------------
__global__ __launch_bounds__(512, 1)
void protomatch_mma(float* __restrict__ out, long long out_size)
{
    extern __shared__ char dsm[];
    const uint32_t dynb = smem_u32(dsm);
    const uint32_t base = (dynb + 1023u) & ~1023u;
    char* base_g = dsm + (base - dynb);
    const uint32_t Asm = base;            // 131072 bytes (8 chunks x 16KB)
    const uint32_t Bsm = base + 131072u;  // 49152 bytes (3 bufs x 16KB)

    const int tid = threadIdx.x, lane = tid & 31, wid = tid >> 5;
    const int warp_m = wid & 3, warp_n = wid >> 2;   // 4 x 4
    const int m0 = blockIdx.x << 7;

    // ---- stage A (128 rows x 512 fp16) + first two B slices ----
    const char* Ag = reinterpret_cast<const char*>(g_a);
    #pragma unroll
    for (int i = 0; i < 16; ++i) {
        int u = tid + (i << 9);          // 0..8191 16B units
        int s = u >> 10;                 // chunk 0..7
        int r = (u >> 3) & 127;          // row 0..127
        int c = u & 7;                   // 16B col 0..7
        uint32_t o = (uint32_t)(r << 7) + (uint32_t)(c << 4);
        cpa16(Asm + (s << 14) + (o ^ ((o >> 3) & 0x70)),
              Ag + (size_t)(m0 + r) * 1024 + (s << 7) + (c << 4));
    }
    load_bslice(Bsm, 0, tid);
    asm volatile("cp.async.commit_group;");
    load_bslice(Bsm, 1, tid);
    asm volatile("cp.async.commit_group;");

    // per-lane ldmatrix address components
    uint32_t aoff[2], aswz[2];
    #pragma unroll
    for (int mt = 0; mt < 2; ++mt) {
        int rowA = warp_m * 32 + mt * 16 + (lane & 15);
        aoff[mt] = (uint32_t)rowA << 7;
        aswz[mt] = (uint32_t)(rowA & 7);
    }
    const uint32_t alc = (uint32_t)(lane >> 4);        // k-half select for A

    uint32_t boff[2], bswz[2];
    #pragma unroll
    for (int nt2 = 0; nt2 < 2; ++nt2) {
        int rowB = warp_n * 32 + nt2 * 16 + ((lane >> 4) << 3) + (lane & 7);
        boff[nt2] = (uint32_t)rowB << 7;
        bswz[nt2] = (uint32_t)(rowB & 7);
    }
    const uint32_t blc = (uint32_t)((lane >> 3) & 1);  // k-half select for B

    float acc[2][4][4];
    float t1v[4], t2v[4];
    int   t1i[4];
    #pragma unroll
    for (int s = 0; s < 4; ++s) { t1v[s] = -CUDART_INF_F; t2v[s] = -CUDART_INF_F; t1i[s] = 0; }

    for (int t = 0; t < 48; ++t) {
        const int pc = t / 12, s = t % 12;
        if (s == 0) {
            #pragma unroll
            for (int i = 0; i < 2; ++i)
                #pragma unroll
                for (int j = 0; j < 4; ++j)
                    #pragma unroll
                    for (int q = 0; q < 4; ++q) acc[i][j][q] = 0.f;
        }
        // pipeline: wait(tile t ready) -> sync -> issue copy t+2 -> compute
        if (t < 47) asm volatile("cp.async.wait_group 1;");
        else        asm volatile("cp.async.wait_group 0;");
        __syncthreads();
        if (t + 2 < 48) {
            load_bslice(Bsm, t + 2, tid);
            asm volatile("cp.async.commit_group;");
        }

        const int a_ch = (s < 8) ? s : (s - 8);
        const uint32_t Ab = Asm + ((uint32_t)a_ch << 14);
        const uint32_t Bb = Bsm + (uint32_t)(t % 3) * 16384u;

        #pragma unroll
        for (int k16 = 0; k16 < 4; ++k16) {
            uint32_t ra[2][4];
            #pragma unroll
            for (int mt = 0; mt < 2; ++mt) {
                uint32_t c16 = (uint32_t)(k16 << 1) + alc;
                LDSM_X4(ra[mt][0], ra[mt][1], ra[mt][2], ra[mt][3],
                        Ab + aoff[mt] + ((c16 ^ aswz[mt]) << 4));
            }
            #pragma unroll
            for (int nt2 = 0; nt2 < 2; ++nt2) {
                uint32_t c16 = (uint32_t)(k16 << 1) + blc;
                uint32_t rb[4];
                LDSM_X4(rb[0], rb[1], rb[2], rb[3],
                        Bb + boff[nt2] + ((c16 ^ bswz[nt2]) << 4));
                MMA16816(acc[0][2*nt2+0], ra[0], (rb + 0));
                MMA16816(acc[1][2*nt2+0], ra[1], (rb + 0));
                MMA16816(acc[0][2*nt2+1], ra[0], (rb + 2));
                MMA16816(acc[1][2*nt2+1], ra[1], (rb + 2));
            }
        }

        if (s == 11) {     // fold chunk pc into running top-2
            #pragma unroll
            for (int mt = 0; mt < 2; ++mt)
                #pragma unroll
                for (int rh = 0; rh < 2; ++rh) {
                    int sl = mt * 2 + rh;
                    #pragma unroll
                    for (int nt = 0; nt < 4; ++nt)
                        #pragma unroll
                        for (int e = 0; e < 2; ++e) {
                            float v = acc[mt][nt][rh * 2 + e];
                            int col = (pc << 7) + (warp_n << 5) + (nt << 3)
                                    + ((lane & 3) << 1) + e;
                            if (v > t1v[sl]) { t2v[sl] = t1v[sl]; t1v[sl] = v; t1i[sl] = col; }
                            else if (v > t2v[sl]) t2v[sl] = v;
                        }
                }
        }
    }
    __syncthreads();

    // ---- cross-lane/warp reduction via smem (reuse A region) ----
    float* sv1 = reinterpret_cast<float*>(base_g);           // [128][16]
    int*   si1 = reinterpret_cast<int*>(base_g + 8192);
    float* sv2 = reinterpret_cast<float*>(base_g + 16384);
    #pragma unroll
    for (int mt = 0; mt < 2; ++mt)
        #pragma unroll
        for (int rh = 0; rh < 2; ++rh) {
            int sl = mt * 2 + rh;
            int row = warp_m * 32 + mt * 16 + rh * 8 + (lane >> 2);
            int cand = (warp_n << 2) + (lane & 3);
            sv1[row * 16 + cand] = t1v[sl];
            si1[row * 16 + cand] = t1i[sl];
            sv2[row * 16 + cand] = t2v[sl];
        }
    __syncthreads();

    if (tid < 128) {
        float v1 = -CUDART_INF_F, v2 = -CUDART_INF_F;
        int i1 = 0x7fffffff;
        #pragma unroll
        for (int c = 0; c < 16; ++c) {
            float cv1 = sv1[tid * 16 + c], cv2 = sv2[tid * 16 + c];
            int   ci1 = si1[tid * 16 + c];
            if (cv1 > v1 || (cv1 == v1 && ci1 < i1)) {
                v2 = fmaxf(v1, cv2); v1 = cv1; i1 = ci1;
            } else {
                v2 = fmaxf(v2, cv1);
            }
        }
        const int m = m0 + tid;
        g_idx[m] = i1;
        if (out_size > 16777216LL) out[16777216 + m] = (float)i1;
        if (v1 - v2 < 1e-4f) {
            int pos = atomicAdd(&g_nfix, 1);
            g_fixlist[pos] = m;
        }
    }
}

// ---------------------------------------------------------------------------
// Fixup: exact fp32 argmax for flagged pixels, 8 entries batched per block
// ---------------------------------------------------------------------------
__global__ __launch_bounds__(256)
void fixup_kernel(const float* __restrict__ x, float* __restrict__ out,
                  long long out_size)
{
    __shared__ __align__(16) float xs[8][260];
    __shared__ float rbv[8][8];
    __shared__ int   rbi[8][8];
    const int tid = threadIdx.x, lane = tid & 31, wid = tid >> 5;
    const int nfix = g_nfix;

    for (int g0 = blockIdx.x * 8; g0 < nfix; g0 += gridDim.x * 8) {
        const int ne = min(8, nfix - g0);
        for (int i = tid; i < (ne << 8); i += 256) {
            int e = i >> 8, c = i & 255;
            int m = g_fixlist[g0 + e];
            xs[e][c] = x[(m >> 10) * 262144 + c * 1024 + (m & 1023)];
        }
        __syncthreads();

        float bv[8]; int bi[8];
        #pragma unroll
        for (int e = 0; e < 8; ++e) { bv[e] = -CUDART_INF_F; bi[e] = 0; }

        #pragma unroll
        for (int h = 0; h < 2; ++h) {
            const int p = tid + (h << 8);
            const float4* pr = reinterpret_cast<const float4*>(g_pnf + (p << 8));
            float acc[8];
            #pragma unroll
            for (int e = 0; e < 8; ++e) acc[e] = 0.f;
            #pragma unroll 4
            for (int c4 = 0; c4 < 64; ++c4) {
                float4 pv = pr[c4];
                #pragma unroll
                for (int e = 0; e < 8; ++e) {
                    float4 xv = reinterpret_cast<const float4*>(xs[e])[c4];
                    acc[e] = fmaf(pv.x, xv.x, acc[e]);
                    acc[e] = fmaf(pv.y, xv.y, acc[e]);
                    acc[e] = fmaf(pv.z, xv.z, acc[e]);
                    acc[e] = fmaf(pv.w, xv.w, acc[e]);
                }
            }
            #pragma unroll
            for (int e = 0; e < 8; ++e)
                if (acc[e] > bv[e]) { bv[e] = acc[e]; bi[e] = p; }  // ascending p
        }

        #pragma unroll
        for (int e = 0; e < 8; ++e) {
            float v = bv[e]; int ix = bi[e];
            #pragma unroll
            for (int s = 16; s >= 1; s >>= 1) {
                float ov = __shfl_xor_sync(0xffffffffu, v, s);
                int   oi = __shfl_xor_sync(0xffffffffu, ix, s);
                if (ov > v || (ov == v && oi < ix)) { v = ov; ix = oi; }
            }
            if (lane == 0) { rbv[e][wid] = v; rbi[e][wid] = ix; }
        }
        __syncthreads();

        if (tid < ne) {
            float fv = rbv[tid][0]; int fi = rbi[tid][0];
            #pragma unroll
            for (int w = 1; w < 8; ++w)
                if (rbv[tid][w] > fv || (rbv[tid][w] == fv && rbi[tid][w] < fi)) {
                    fv = rbv[tid][w]; fi = rbi[tid][w];
                }
            const int m = g_fixlist[g0 + tid];
            g_idx[m] = fi;
            if (out_size > 16777216LL) out[16777216 + m] = (float)fi;
        }
        __syncthreads();
    }
}

// ---------------------------------------------------------------------------
// Gather: recon[b,c,h,w] = proto[idx[pixel]][c], coalesced
// ---------------------------------------------------------------------------
__global__ __launch_bounds__(256)
void gather_kernel(const float* __restrict__ proto, float* __restrict__ out)
{
    __shared__ int sIdx[128];
    const int tid = threadIdx.x;
    const int m0 = blockIdx.x << 7, b = m0 >> 10, n0 = m0 & 1023;
    if (tid < 128) sIdx[tid] = g_idx[m0 + tid];
    __syncthreads();
    const int n4 = tid & 31, co = tid >> 5;
    const float* r0 = proto + (sIdx[(n4 << 2) + 0] << 8);
    const float* r1 = proto + (sIdx[(n4 << 2) + 1] << 8);
    const float* r2 = proto + (sIdx[(n4 << 2) + 2] << 8);
    const float* r3 = proto + (sIdx[(n4 << 2) + 3] << 8);
    float4* Og = reinterpret_cast<float4*>(out) + (b * 65536 + (n0 >> 2) + n4);
    #pragma unroll 4
    for (int c = co; c < 256; c += 8)
        Og[c * 256] = make_float4(r0[c], r1[c], r2[c], r3[c]);
}

// ---------------------------------------------------------------------------
extern "C" void kernel_launch(void* const* d_in, const int* in_sizes, int n_in,
                              void* d_out, int out_size)
{
    const float* x     = (const float*)d_in[0];
    const float* proto = (const float*)d_in[1];
    if (n_in >= 2 && in_sizes[0] == 512 * 256 && in_sizes[1] != 512 * 256) {
        proto = (const float*)d_in[0];
        x     = (const float*)d_in[1];
    }
    float* out = (float*)d_out;

    proto_prep_kernel<<<512, 256>>>(proto);
    xsplit_kernel<<<dim3(8, 32, 64), 256>>>(x);

    cudaFuncSetAttribute(protomatch_mma,
                         cudaFuncAttributeMaxDynamicSharedMemorySize, 181248);
    protomatch_mma<<<512, 512, 181248>>>(out, (long long)out_size);

    fixup_kernel<<<128, 256>>>(x, out, (long long)out_size);
    gather_kernel<<<512, 256>>>(proto, out);
}

// round 9
// speedup vs baseline: 2.6069x; 1.5855x over previous
#include <cuda_runtime.h>
#include <cuda_fp16.h>
#include <cstdint>
#include <math_constants.h>

// ---------------------------------------------------------------------------
// Device scratch (static: allocation-free)
// ---------------------------------------------------------------------------
__device__ __half g_a [65536 * 256];   // A pixel-major [m][c] = fp16(x)
__device__ __half g_bh[512 * 256];     // normalized proto fp16 [p][c]
__device__ float  g_pnf[512 * 256];    // normalized protos fp32 (for fixup)
__device__ int    g_idx[65536];        // per-pixel argmax
__device__ int    g_fixlist[65536];
__device__ int    g_nfix;

__device__ __forceinline__ uint32_t smem_u32(const void* p) {
    uint32_t a;
    asm("{ .reg .u64 t; cvta.to.shared.u64 t, %1; cvt.u32.u64 %0, t; }"
        : "=r"(a) : "l"(p));
    return a;
}
__device__ __forceinline__ void cpa16(uint32_t dst, const void* src) {
    asm volatile("cp.async.cg.shared.global [%0], [%1], 16;"
                 :: "r"(dst), "l"(src));
}
#define LDSM_X4(r0,r1,r2,r3,addr) \
    asm volatile("ldmatrix.sync.aligned.m8n8.x4.shared.b16 {%0,%1,%2,%3}, [%4];" \
        : "=r"(r0),"=r"(r1),"=r"(r2),"=r"(r3) : "r"(addr))
#define MMA16816(d,a,b) \
    asm volatile("mma.sync.aligned.m16n8k16.row.col.f32.f16.f16.f32 " \
        "{%0,%1,%2,%3},{%4,%5,%6,%7},{%8,%9},{%0,%1,%2,%3};" \
        : "+f"(d[0]),"+f"(d[1]),"+f"(d[2]),"+f"(d[3]) \
        : "r"(a[0]),"r"(a[1]),"r"(a[2]),"r"(a[3]),"r"(b[0]),"r"(b[1]))

// fp16-GEMM absolute error is < ~3.2e-4 std; 4e-3 threshold = ~12 sigma.
#define FIX_THRESH 4e-3f

// ---------------------------------------------------------------------------
// Prep 1: normalize protos -> fp16 + fp32 copies; reset fix counter
// ---------------------------------------------------------------------------
__global__ void proto_prep_kernel(const float* __restrict__ proto) {
    __shared__ float sred[8];
    const int p = blockIdx.x, c = threadIdx.x;
    float v = proto[(p << 8) + c];
    float ss = v * v;
    #pragma unroll
    for (int s = 16; s >= 1; s >>= 1) ss += __shfl_xor_sync(0xffffffffu, ss, s);
    if ((c & 31) == 0) sred[c >> 5] = ss;
    __syncthreads();
    float tot = 0.f;
    #pragma unroll
    for (int w = 0; w < 8; ++w) tot += sred[w];
    const float pn = v / fmaxf(sqrtf(tot), 1e-12f);
    g_pnf[(p << 8) + c] = pn;
    g_bh[(p << 8) + c] = __float2half(pn);
    if (p == 0 && c == 0) g_nfix = 0;
}

// ---------------------------------------------------------------------------
// Prep 2: transpose x [b][c][m] -> A [m][c] fp16
// ---------------------------------------------------------------------------
__global__ void xsplit_kernel(const float* __restrict__ x) {
    __shared__ float t[32][33];
    const int b = blockIdx.z, c0 = blockIdx.x << 5, m0 = blockIdx.y << 5;
    const int tx = threadIdx.x & 31, ty = threadIdx.x >> 5;
    #pragma unroll
    for (int i = 0; i < 4; ++i) {
        int c = ty + (i << 3);
        t[c][tx] = x[b * 262144 + (c0 + c) * 1024 + m0 + tx];
    }
    __syncthreads();
    #pragma unroll
    for (int i = 0; i < 4; ++i) {
        int m = ty + (i << 3);
        g_a[((size_t)(b * 1024 + m0 + m) << 8) + c0 + tx] = __float2half(t[tx][m]);
    }
}

// ---------------------------------------------------------------------------
// B slice loader (512 threads): 128 protos x 64 ch fp16 = 16KB into buf (t%3).
// Slice t: proto-chunk pc = t/4, k-chunk kb = t%4.
// ---------------------------------------------------------------------------
__device__ __forceinline__ void load_bslice(uint32_t Bsm, int t, int tid) {
    const int pc = t >> 2, kb = t & 3;
    const char* src0 = reinterpret_cast<const char*>(g_bh);
    const uint32_t dst = Bsm + (uint32_t)(t % 3) * 16384u;
    #pragma unroll
    for (int i = 0; i < 2; ++i) {
        int u = tid + (i << 9);          // 0..1023 16B units
        int r = u >> 3, c = u & 7;
        uint32_t o = (uint32_t)(r << 7) + (uint32_t)(c << 4);
        const char* src = src0 + (size_t)(pc * 128 + r) * 512 + kb * 128 + (c << 4);
        cpa16(dst + (o ^ ((o >> 3) & 0x70)), src);
    }
}

// ---------------------------------------------------------------------------
// Main: 512 blocks x 128 pixels, 512 threads (16 warps, 4x4 warp grid).
// A (128x256 fp16, 64KB) staged once; 16 B slices (16KB) 3-stage pipelined.
// Plain fp16 GEMM (hh term only), fp32 acc, top-2 epilogue + fixup flags.
// ---------------------------------------------------------------------------
__global__ __launch_bounds__(512, 1)
void protomatch_mma(float* __restrict__ out, long long out_size)
{
    extern __shared__ char dsm[];
    const uint32_t dynb = smem_u32(dsm);
    const uint32_t base = (dynb + 1023u) & ~1023u;
    char* base_g = dsm + (base - dynb);
    const uint32_t Asm = base;            // 65536 bytes (4 chunks x 16KB)
    const uint32_t Bsm = base + 65536u;   // 49152 bytes (3 bufs x 16KB)

    const int tid = threadIdx.x, lane = tid & 31, wid = tid >> 5;
    const int warp_m = wid & 3, warp_n = wid >> 2;   // 4 x 4
    const int m0 = blockIdx.x << 7;

    // ---- stage A (128 rows x 256 fp16) + first two B slices ----
    const char* Ag = reinterpret_cast<const char*>(g_a);
    #pragma unroll
    for (int i = 0; i < 8; ++i) {
        int u = tid + (i << 9);          // 0..4095 16B units
        int s = u >> 10;                 // chunk 0..3
        int r = (u >> 3) & 127;          // row 0..127
        int c = u & 7;                   // 16B col 0..7
        uint32_t o = (uint32_t)(r << 7) + (uint32_t)(c << 4);
        cpa16(Asm + (s << 14) + (o ^ ((o >> 3) & 0x70)),
              Ag + (size_t)(m0 + r) * 512 + (s << 7) + (c << 4));
    }
    load_bslice(Bsm, 0, tid);
    asm volatile("cp.async.commit_group;");
    load_bslice(Bsm, 1, tid);
    asm volatile("cp.async.commit_group;");

    // per-lane ldmatrix address components
    uint32_t aoff[2], aswz[2];
    #pragma unroll
    for (int mt = 0; mt < 2; ++mt) {
        int rowA = warp_m * 32 + mt * 16 + (lane & 15);
        aoff[mt] = (uint32_t)rowA << 7;
        aswz[mt] = (uint32_t)(rowA & 7);
    }
    const uint32_t alc = (uint32_t)(lane >> 4);        // k-half select for A

    uint32_t boff[2], bswz[2];
    #pragma unroll
    for (int nt2 = 0; nt2 < 2; ++nt2) {
        int rowB = warp_n * 32 + nt2 * 16 + ((lane >> 4) << 3) + (lane & 7);
        boff[nt2] = (uint32_t)rowB << 7;
        bswz[nt2] = (uint32_t)(rowB & 7);
    }
    const uint32_t blc = (uint32_t)((lane >> 3) & 1);  // k-half select for B

    float acc[2][4][4];
    float t1v[4], t2v[4];
    int   t1i[4];
    #pragma unroll
    for (int s = 0; s < 4; ++s) { t1v[s] = -CUDART_INF_F; t2v[s] = -CUDART_INF_F; t1i[s] = 0; }

    for (int t = 0; t < 16; ++t) {
        const int pc = t >> 2, kb = t & 3;
        if (kb == 0) {
            #pragma unroll
            for (int i = 0; i < 2; ++i)
                #pragma unroll
                for (int j = 0; j < 4; ++j)
                    #pragma unroll
                    for (int q = 0; q < 4; ++q) acc[i][j][q] = 0.f;
        }
        // pipeline: wait(tile t ready) -> sync -> issue copy t+2 -> compute
        if (t < 15) asm volatile("cp.async.wait_group 1;");
        else        asm volatile("cp.async.wait_group 0;");
        __syncthreads();
        if (t + 2 < 16) {
            load_bslice(Bsm, t + 2, tid);
            asm volatile("cp.async.commit_group;");
        }

        const uint32_t Ab = Asm + ((uint32_t)kb << 14);
        const uint32_t Bb = Bsm + (uint32_t)(t % 3) * 16384u;

        #pragma unroll
        for (int k16 = 0; k16 < 4; ++k16) {
            uint32_t ra[2][4];
            #pragma unroll
            for (int mt = 0; mt < 2; ++mt) {
                uint32_t c16 = (uint32_t)(k16 << 1) + alc;
                LDSM_X4(ra[mt][0], ra[mt][1], ra[mt][2], ra[mt][3],
                        Ab + aoff[mt] + ((c16 ^ aswz[mt]) << 4));
            }
            #pragma unroll
            for (int nt2 = 0; nt2 < 2; ++nt2) {
                uint32_t c16 = (uint32_t)(k16 << 1) + blc;
                uint32_t rb[4];
                LDSM_X4(rb[0], rb[1], rb[2], rb[3],
                        Bb + boff[nt2] + ((c16 ^ bswz[nt2]) << 4));
                MMA16816(acc[0][2*nt2+0], ra[0], (rb + 0));
                MMA16816(acc[1][2*nt2+0], ra[1], (rb + 0));
                MMA16816(acc[0][2*nt2+1], ra[0], (rb + 2));
                MMA16816(acc[1][2*nt2+1], ra[1], (rb + 2));
            }
        }

        if (kb == 3) {     // fold chunk pc into running top-2
            #pragma unroll
            for (int mt = 0; mt < 2; ++mt)
                #pragma unroll
                for (int rh = 0; rh < 2; ++rh) {
                    int sl = mt * 2 + rh;
                    #pragma unroll
                    for (int nt = 0; nt < 4; ++nt)
                        #pragma unroll
                        for (int e = 0; e < 2; ++e) {
                            float v = acc[mt][nt][rh * 2 + e];
                            int col = (pc << 7) + (warp_n << 5) + (nt << 3)
                                    + ((lane & 3) << 1) + e;
                            if (v > t1v[sl]) { t2v[sl] = t1v[sl]; t1v[sl] = v; t1i[sl] = col; }
                            else if (v > t2v[sl]) t2v[sl] = v;
                        }
                }
        }
    }
    __syncthreads();

    // ---- cross-lane/warp reduction via smem (reuse A region) ----
    float* sv1 = reinterpret_cast<float*>(base_g);           // [128][16]
    int*   si1 = reinterpret_cast<int*>(base_g + 8192);
    float* sv2 = reinterpret_cast<float*>(base_g + 16384);
    #pragma unroll
    for (int mt = 0; mt < 2; ++mt)
        #pragma unroll
        for (int rh = 0; rh < 2; ++rh) {
            int sl = mt * 2 + rh;
            int row = warp_m * 32 + mt * 16 + rh * 8 + (lane >> 2);
            int cand = (warp_n << 2) + (lane & 3);
            sv1[row * 16 + cand] = t1v[sl];
            si1[row * 16 + cand] = t1i[sl];
            sv2[row * 16 + cand] = t2v[sl];
        }
    __syncthreads();

    if (tid < 128) {
        float v1 = -CUDART_INF_F, v2 = -CUDART_INF_F;
        int i1 = 0x7fffffff;
        #pragma unroll
        for (int c = 0; c < 16; ++c) {
            float cv1 = sv1[tid * 16 + c], cv2 = sv2[tid * 16 + c];
            int   ci1 = si1[tid * 16 + c];
            if (cv1 > v1 || (cv1 == v1 && ci1 < i1)) {
                v2 = fmaxf(v1, cv2); v1 = cv1; i1 = ci1;
            } else {
                v2 = fmaxf(v2, cv1);
            }
        }
        const int m = m0 + tid;
        g_idx[m] = i1;
        if (out_size > 16777216LL) out[16777216 + m] = (float)i1;
        if (v1 - v2 < FIX_THRESH) {
            int pos = atomicAdd(&g_nfix, 1);
            g_fixlist[pos] = m;
        }
    }
}

// ---------------------------------------------------------------------------
// Fixup: exact fp32 argmax for flagged pixels, 8 entries batched per block
// ---------------------------------------------------------------------------
__global__ __launch_bounds__(256)
void fixup_kernel(const float* __restrict__ x, float* __restrict__ out,
                  long long out_size)
{
    __shared__ __align__(16) float xs[8][260];
    __shared__ float rbv[8][8];
    __shared__ int   rbi[8][8];
    const int tid = threadIdx.x, lane = tid & 31, wid = tid >> 5;
    const int nfix = g_nfix;

    for (int g0 = blockIdx.x * 8; g0 < nfix; g0 += gridDim.x * 8) {
        const int ne = min(8, nfix - g0);
        for (int i = tid; i < (ne << 8); i += 256) {
            int e = i >> 8, c = i & 255;
            int m = g_fixlist[g0 + e];
            xs[e][c] = x[(m >> 10) * 262144 + c * 1024 + (m & 1023)];
        }
        __syncthreads();

        float bv[8]; int bi[8];
        #pragma unroll
        for (int e = 0; e < 8; ++e) { bv[e] = -CUDART_INF_F; bi[e] = 0; }

        #pragma unroll
        for (int h = 0; h < 2; ++h) {
            const int p = tid + (h << 8);
            const float4* pr = reinterpret_cast<const float4*>(g_pnf + (p << 8));
            float acc[8];
            #pragma unroll
            for (int e = 0; e < 8; ++e) acc[e] = 0.f;
            #pragma unroll 4
            for (int c4 = 0; c4 < 64; ++c4) {
                float4 pv = pr[c4];
                #pragma unroll
                for (int e = 0; e < 8; ++e) {
                    float4 xv = reinterpret_cast<const float4*>(xs[e])[c4];
                    acc[e] = fmaf(pv.x, xv.x, acc[e]);
                    acc[e] = fmaf(pv.y, xv.y, acc[e]);
                    acc[e] = fmaf(pv.z, xv.z, acc[e]);
                    acc[e] = fmaf(pv.w, xv.w, acc[e]);
                }
            }
            #pragma unroll
            for (int e = 0; e < 8; ++e)
                if (acc[e] > bv[e]) { bv[e] = acc[e]; bi[e] = p; }  // ascending p
        }

        #pragma unroll
        for (int e = 0; e < 8; ++e) {
            float v = bv[e]; int ix = bi[e];
            #pragma unroll
            for (int s = 16; s >= 1; s >>= 1) {
                float ov = __shfl_xor_sync(0xffffffffu, v, s);
                int   oi = __shfl_xor_sync(0xffffffffu, ix, s);
                if (ov > v || (ov == v && oi < ix)) { v = ov; ix = oi; }
            }
            if (lane == 0) { rbv[e][wid] = v; rbi[e][wid] = ix; }
        }
        __syncthreads();

        if (tid < ne) {
            float fv = rbv[tid][0]; int fi = rbi[tid][0];
            #pragma unroll
            for (int w = 1; w < 8; ++w)
                if (rbv[tid][w] > fv || (rbv[tid][w] == fv && rbi[tid][w] < fi)) {
                    fv = rbv[tid][w]; fi = rbi[tid][w];
                }
            const int m = g_fixlist[g0 + tid];
            g_idx[m] = fi;
            if (out_size > 16777216LL) out[16777216 + m] = (float)fi;
        }
        __syncthreads();
    }
}

// ---------------------------------------------------------------------------
// Gather: recon[b,c,h,w] = proto[idx[pixel]][c], coalesced
// ---------------------------------------------------------------------------
__global__ __launch_bounds__(256)
void gather_kernel(const float* __restrict__ proto, float* __restrict__ out)
{
    __shared__ int sIdx[128];
    const int tid = threadIdx.x;
    const int m0 = blockIdx.x << 7, b = m0 >> 10, n0 = m0 & 1023;
    if (tid < 128) sIdx[tid] = g_idx[m0 + tid];
    __syncthreads();
    const int n4 = tid & 31, co = tid >> 5;
    const float* r0 = proto + (sIdx[(n4 << 2) + 0] << 8);
    const float* r1 = proto + (sIdx[(n4 << 2) + 1] << 8);
    const float* r2 = proto + (sIdx[(n4 << 2) + 2] << 8);
    const float* r3 = proto + (sIdx[(n4 << 2) + 3] << 8);
    float4* Og = reinterpret_cast<float4*>(out) + (b * 65536 + (n0 >> 2) + n4);
    #pragma unroll 4
    for (int c = co; c < 256; c += 8)
        Og[c * 256] = make_float4(r0[c], r1[c], r2[c], r3[c]);
}

// ---------------------------------------------------------------------------
extern "C" void kernel_launch(void* const* d_in, const int* in_sizes, int n_in,
                              void* d_out, int out_size)
{
    const float* x     = (const float*)d_in[0];
    const float* proto = (const float*)d_in[1];
    if (n_in >= 2 && in_sizes[0] == 512 * 256 && in_sizes[1] != 512 * 256) {
        proto = (const float*)d_in[0];
        x     = (const float*)d_in[1];
    }
    float* out = (float*)d_out;

    proto_prep_kernel<<<512, 256>>>(proto);
    xsplit_kernel<<<dim3(8, 32, 64), 256>>>(x);

    cudaFuncSetAttribute(protomatch_mma,
                         cudaFuncAttributeMaxDynamicSharedMemorySize, 135168);
    protomatch_mma<<<512, 512, 135168>>>(out, (long long)out_size);

    fixup_kernel<<<128, 256>>>(x, out, (long long)out_size);
    gather_kernel<<<512, 256>>>(proto, out);
}

// round 10
// speedup vs baseline: 2.6190x; 1.0046x over previous
#include <cuda_runtime.h>
#include <cuda_fp16.h>
#include <cstdint>
#include <math_constants.h>

// ---------------------------------------------------------------------------
// Device scratch (static: allocation-free)
// ---------------------------------------------------------------------------
__device__ __half g_a [65536 * 256];   // A pixel-major [m][c] = fp16(x)
__device__ __half g_bh[512 * 256];     // normalized proto fp16 [p][c]
__device__ float  g_pnf[512 * 256];    // normalized protos fp32 (for fixup)
__device__ int    g_fixlist[65536];
__device__ int    g_nfix;

__device__ __forceinline__ uint32_t smem_u32(const void* p) {
    uint32_t a;
    asm("{ .reg .u64 t; cvta.to.shared.u64 t, %1; cvt.u32.u64 %0, t; }"
        : "=r"(a) : "l"(p));
    return a;
}
__device__ __forceinline__ void cpa16(uint32_t dst, const void* src) {
    asm volatile("cp.async.cg.shared.global [%0], [%1], 16;"
                 :: "r"(dst), "l"(src));
}
#define LDSM_X4(r0,r1,r2,r3,addr) \
    asm volatile("ldmatrix.sync.aligned.m8n8.x4.shared.b16 {%0,%1,%2,%3}, [%4];" \
        : "=r"(r0),"=r"(r1),"=r"(r2),"=r"(r3) : "r"(addr))
#define MMA16816(d,a,b) \
    asm volatile("mma.sync.aligned.m16n8k16.row.col.f32.f16.f16.f32 " \
        "{%0,%1,%2,%3},{%4,%5,%6,%7},{%8,%9},{%0,%1,%2,%3};" \
        : "+f"(d[0]),"+f"(d[1]),"+f"(d[2]),"+f"(d[3]) \
        : "r"(a[0]),"r"(a[1]),"r"(a[2]),"r"(a[3]),"r"(b[0]),"r"(b[1]))

// fp16-GEMM absolute error < ~3.2e-4 std; 4e-3 threshold = ~12 sigma.
#define FIX_THRESH 4e-3f

// ---------------------------------------------------------------------------
// Prep 1: normalize protos -> fp16 + fp32 copies; reset fix counter
// ---------------------------------------------------------------------------
__global__ void proto_prep_kernel(const float* __restrict__ proto) {
    __shared__ float sred[8];
    const int p = blockIdx.x, c = threadIdx.x;
    float v = proto[(p << 8) + c];
    float ss = v * v;
    #pragma unroll
    for (int s = 16; s >= 1; s >>= 1) ss += __shfl_xor_sync(0xffffffffu, ss, s);
    if ((c & 31) == 0) sred[c >> 5] = ss;
    __syncthreads();
    float tot = 0.f;
    #pragma unroll
    for (int w = 0; w < 8; ++w) tot += sred[w];
    const float pn = v / fmaxf(sqrtf(tot), 1e-12f);
    g_pnf[(p << 8) + c] = pn;
    g_bh[(p << 8) + c] = __float2half(pn);
    if (p == 0 && c == 0) g_nfix = 0;
}

// ---------------------------------------------------------------------------
// Prep 2: transpose x [b][c][m] -> A [m][c] fp16
// ---------------------------------------------------------------------------
__global__ void xsplit_kernel(const float* __restrict__ x) {
    __shared__ float t[32][33];
    const int b = blockIdx.z, c0 = blockIdx.x << 5, m0 = blockIdx.y << 5;
    const int tx = threadIdx.x & 31, ty = threadIdx.x >> 5;
    #pragma unroll
    for (int i = 0; i < 4; ++i) {
        int c = ty + (i << 3);
        t[c][tx] = x[b * 262144 + (c0 + c) * 1024 + m0 + tx];
    }
    __syncthreads();
    #pragma unroll
    for (int i = 0; i < 4; ++i) {
        int m = ty + (i << 3);
        g_a[((size_t)(b * 1024 + m0 + m) << 8) + c0 + tx] = __float2half(t[tx][m]);
    }
}

// ---------------------------------------------------------------------------
// B slice loader (512 threads): 128 protos x 64 ch fp16 = 16KB into buf (t%3).
// Slice t: proto-chunk pc = t/4, k-chunk kb = t%4.
// ---------------------------------------------------------------------------
__device__ __forceinline__ void load_bslice(uint32_t Bsm, int t, int tid) {
    const int pc = t >> 2, kb = t & 3;
    const char* src0 = reinterpret_cast<const char*>(g_bh);
    const uint32_t dst = Bsm + (uint32_t)(t % 3) * 16384u;
    #pragma unroll
    for (int i = 0; i < 2; ++i) {
        int u = tid + (i << 9);          // 0..1023 16B units
        int r = u >> 3, c = u & 7;
        uint32_t o = (uint32_t)(r << 7) + (uint32_t)(c << 4);
        const char* src = src0 + (size_t)(pc * 128 + r) * 512 + kb * 128 + (c << 4);
        cpa16(dst + (o ^ ((o >> 3) & 0x70)), src);
    }
}

// ---------------------------------------------------------------------------
// Main: 256 blocks x 256 pixels, 512 threads (16 warps, 4m x 4n warp grid,
// 64x32 tile/warp). A (256x256 fp16, 128KB) staged once; 16 B slices (16KB)
// 3-stage pipelined. fp16 GEMM, fp32 acc, top-2 + fused gather epilogue.
// ---------------------------------------------------------------------------
__global__ __launch_bounds__(512, 1)
void protomatch_mma(const float* __restrict__ proto,
                    float* __restrict__ out, long long out_size)
{
    extern __shared__ char dsm[];
    const uint32_t dynb = smem_u32(dsm);
    const uint32_t base = (dynb + 1023u) & ~1023u;
    char* base_g = dsm + (base - dynb);
    const uint32_t Asm = base;            // 131072 bytes (4 chunks x 32KB)
    const uint32_t Bsm = base + 131072u;  // 49152 bytes (3 bufs x 16KB)

    const int tid = threadIdx.x, lane = tid & 31, wid = tid >> 5;
    const int warp_m = wid & 3, warp_n = wid >> 2;   // 4 x 4
    const int m0 = blockIdx.x << 8;      // 256 pixels per block
    const int b = m0 >> 10, n0 = m0 & 1023;

    // ---- stage A (256 rows x 256 fp16 = 128KB) + first two B slices ----
    const char* Ag = reinterpret_cast<const char*>(g_a);
    #pragma unroll
    for (int i = 0; i < 16; ++i) {
        int u = tid + (i << 9);          // 0..8191 16B units
        int s = u >> 11;                 // chunk 0..3 (2048 units each)
        int r = (u >> 3) & 255;          // row 0..255
        int c = u & 7;                   // 16B col 0..7
        uint32_t o = (uint32_t)(r << 7) + (uint32_t)(c << 4);
        cpa16(Asm + (s << 15) + (o ^ ((o >> 3) & 0x70)),
              Ag + (size_t)(m0 + r) * 512 + (s << 7) + (c << 4));
    }
    load_bslice(Bsm, 0, tid);
    asm volatile("cp.async.commit_group;");
    load_bslice(Bsm, 1, tid);
    asm volatile("cp.async.commit_group;");

    // per-lane ldmatrix address components: 4 m-tiles of 16 rows per warp
    uint32_t aoff[4], aswz[4];
    #pragma unroll
    for (int mt = 0; mt < 4; ++mt) {
        int rowA = warp_m * 64 + mt * 16 + (lane & 15);
        aoff[mt] = (uint32_t)rowA << 7;
        aswz[mt] = (uint32_t)(rowA & 7);
    }
    const uint32_t alc = (uint32_t)(lane >> 4);        // k-half select for A

    uint32_t boff[2], bswz[2];
    #pragma unroll
    for (int nt2 = 0; nt2 < 2; ++nt2) {
        int rowB = warp_n * 32 + nt2 * 16 + ((lane >> 4) << 3) + (lane & 7);
        boff[nt2] = (uint32_t)rowB << 7;
        bswz[nt2] = (uint32_t)(rowB & 7);
    }
    const uint32_t blc = (uint32_t)((lane >> 3) & 1);  // k-half select for B

    float acc[4][4][4];
    float t1v[8], t2v[8];
    int   t1i[8];
    #pragma unroll
    for (int s = 0; s < 8; ++s) { t1v[s] = -CUDART_INF_F; t2v[s] = -CUDART_INF_F; t1i[s] = 0; }

    for (int t = 0; t < 16; ++t) {
        const int pc = t >> 2, kb = t & 3;
        if (kb == 0) {
            #pragma unroll
            for (int i = 0; i < 4; ++i)
                #pragma unroll
                for (int j = 0; j < 4; ++j)
                    #pragma unroll
                    for (int q = 0; q < 4; ++q) acc[i][j][q] = 0.f;
        }
        // pipeline: wait(tile t ready) -> sync -> issue copy t+2 -> compute
        if (t < 15) asm volatile("cp.async.wait_group 1;");
        else        asm volatile("cp.async.wait_group 0;");
        __syncthreads();
        if (t + 2 < 16) {
            load_bslice(Bsm, t + 2, tid);
            asm volatile("cp.async.commit_group;");
        }

        const uint32_t Ab = Asm + ((uint32_t)kb << 15);
        const uint32_t Bb = Bsm + (uint32_t)(t % 3) * 16384u;

        #pragma unroll
        for (int k16 = 0; k16 < 4; ++k16) {
            uint32_t ra[4][4];
            #pragma unroll
            for (int mt = 0; mt < 4; ++mt) {
                uint32_t c16 = (uint32_t)(k16 << 1) + alc;
                LDSM_X4(ra[mt][0], ra[mt][1], ra[mt][2], ra[mt][3],
                        Ab + aoff[mt] + ((c16 ^ aswz[mt]) << 4));
            }
            #pragma unroll
            for (int nt2 = 0; nt2 < 2; ++nt2) {
                uint32_t c16 = (uint32_t)(k16 << 1) + blc;
                uint32_t rb[4];
                LDSM_X4(rb[0], rb[1], rb[2], rb[3],
                        Bb + boff[nt2] + ((c16 ^ bswz[nt2]) << 4));
                #pragma unroll
                for (int mt = 0; mt < 4; ++mt) {
                    MMA16816(acc[mt][2*nt2+0], ra[mt], (rb + 0));
                    MMA16816(acc[mt][2*nt2+1], ra[mt], (rb + 2));
                }
            }
        }

        if (kb == 3) {     // fold chunk pc into running top-2
            #pragma unroll
            for (int mt = 0; mt < 4; ++mt)
                #pragma unroll
                for (int rh = 0; rh < 2; ++rh) {
                    int sl = mt * 2 + rh;
                    #pragma unroll
                    for (int nt = 0; nt < 4; ++nt)
                        #pragma unroll
                        for (int e = 0; e < 2; ++e) {
                            float v = acc[mt][nt][rh * 2 + e];
                            int col = (pc << 7) + (warp_n << 5) + (nt << 3)
                                    + ((lane & 3) << 1) + e;
                            if (v > t1v[sl]) { t2v[sl] = t1v[sl]; t1v[sl] = v; t1i[sl] = col; }
                            else if (v > t2v[sl]) t2v[sl] = v;
                        }
                }
        }
    }
    __syncthreads();

    // ---- cross-lane/warp reduction via smem (reuse A region) ----
    float* sv1 = reinterpret_cast<float*>(base_g);            // [256][16]
    int*   si1 = reinterpret_cast<int*>(base_g + 16384);
    float* sv2 = reinterpret_cast<float*>(base_g + 32768);
    int*   sIdx = reinterpret_cast<int*>(base_g + 49152);     // [256]
    #pragma unroll
    for (int mt = 0; mt < 4; ++mt)
        #pragma unroll
        for (int rh = 0; rh < 2; ++rh) {
            int sl = mt * 2 + rh;
            int row = warp_m * 64 + mt * 16 + rh * 8 + (lane >> 2);
            int cand = (warp_n << 2) + (lane & 3);
            sv1[row * 16 + cand] = t1v[sl];
            si1[row * 16 + cand] = t1i[sl];
            sv2[row * 16 + cand] = t2v[sl];
        }
    __syncthreads();

    if (tid < 256) {
        float v1 = -CUDART_INF_F, v2 = -CUDART_INF_F;
        int i1 = 0x7fffffff;
        #pragma unroll
        for (int c = 0; c < 16; ++c) {
            float cv1 = sv1[tid * 16 + c], cv2 = sv2[tid * 16 + c];
            int   ci1 = si1[tid * 16 + c];
            if (cv1 > v1 || (cv1 == v1 && ci1 < i1)) {
                v2 = fmaxf(v1, cv2); v1 = cv1; i1 = ci1;
            } else {
                v2 = fmaxf(v2, cv1);
            }
        }
        const int m = m0 + tid;
        sIdx[tid] = i1;
        if (out_size > 16777216LL) out[16777216 + m] = (float)i1;
        if (v1 - v2 < FIX_THRESH) {
            int pos = atomicAdd(&g_nfix, 1);
            g_fixlist[pos] = m;
        }
    }
    __syncthreads();

    // ---- fused gather: recon[b,c,h,w] = proto[idx][c], coalesced ----
    const int n4 = tid & 63;   // float4 col within 256-pixel tile
    const int ph = tid >> 6;   // channel phase 0..7
    const float* r0 = proto + (sIdx[(n4 << 2) + 0] << 8);
    const float* r1 = proto + (sIdx[(n4 << 2) + 1] << 8);
    const float* r2 = proto + (sIdx[(n4 << 2) + 2] << 8);
    const float* r3 = proto + (sIdx[(n4 << 2) + 3] << 8);
    float4* Og = reinterpret_cast<float4*>(out) + (b * 65536 + (n0 >> 2) + n4);
    #pragma unroll 4
    for (int c = ph; c < 256; c += 8)
        Og[c * 256] = make_float4(r0[c], r1[c], r2[c], r3[c]);
}

// ---------------------------------------------------------------------------
// Fixup: exact fp32 argmax for flagged pixels, 16/block; patches out rows.
// ---------------------------------------------------------------------------
__global__ __launch_bounds__(256)
void fixup_kernel(const float* __restrict__ x, const float* __restrict__ proto,
                  float* __restrict__ out, long long out_size)
{
    __shared__ __align__(16) float xs[16][260];
    __shared__ float rbv[16][8];
    __shared__ int   rbi[16][8];
    __shared__ int   sfi[16];
    const int tid = threadIdx.x, lane = tid & 31, wid = tid >> 5;
    const int nfix = g_nfix;

    for (int g0 = blockIdx.x * 16; g0 < nfix; g0 += gridDim.x * 16) {
        const int ne = min(16, nfix - g0);
        for (int i = tid; i < (ne << 8); i += 256) {
            int e = i >> 8, c = i & 255;
            int m = g_fixlist[g0 + e];
            xs[e][c] = x[(m >> 10) * 262144 + c * 1024 + (m & 1023)];
        }
        __syncthreads();

        float bv[16]; int bi[16];
        #pragma unroll
        for (int e = 0; e < 16; ++e) { bv[e] = -CUDART_INF_F; bi[e] = 0; }

        #pragma unroll
        for (int h = 0; h < 2; ++h) {
            const int p = tid + (h << 8);
            const float4* pr = reinterpret_cast<const float4*>(g_pnf + (p << 8));
            float acc[16];
            #pragma unroll
            for (int e = 0; e < 16; ++e) acc[e] = 0.f;
            #pragma unroll 2
            for (int c4 = 0; c4 < 64; ++c4) {
                float4 pv = pr[c4];
                #pragma unroll
                for (int e = 0; e < 16; ++e) {
                    float4 xv = reinterpret_cast<const float4*>(xs[e])[c4];
                    acc[e] = fmaf(pv.x, xv.x, acc[e]);
                    acc[e] = fmaf(pv.y, xv.y, acc[e]);
                    acc[e] = fmaf(pv.z, xv.z, acc[e]);
                    acc[e] = fmaf(pv.w, xv.w, acc[e]);
                }
            }
            #pragma unroll
            for (int e = 0; e < 16; ++e)
                if (acc[e] > bv[e]) { bv[e] = acc[e]; bi[e] = p; }  // ascending p
        }

        #pragma unroll
        for (int e = 0; e < 16; ++e) {
            float v = bv[e]; int ix = bi[e];
            #pragma unroll
            for (int s = 16; s >= 1; s >>= 1) {
                float ov = __shfl_xor_sync(0xffffffffu, v, s);
                int   oi = __shfl_xor_sync(0xffffffffu, ix, s);
                if (ov > v || (ov == v && oi < ix)) { v = ov; ix = oi; }
            }
            if (lane == 0) { rbv[e][wid] = v; rbi[e][wid] = ix; }
        }
        __syncthreads();

        if (tid < ne) {
            float fv = rbv[tid][0]; int fi = rbi[tid][0];
            #pragma unroll
            for (int w = 1; w < 8; ++w)
                if (rbv[tid][w] > fv || (rbv[tid][w] == fv && rbi[tid][w] < fi)) {
                    fv = rbv[tid][w]; fi = rbi[tid][w];
                }
            sfi[tid] = fi;
            const int m = g_fixlist[g0 + tid];
            if (out_size > 16777216LL) out[16777216 + m] = (float)fi;
        }
        __syncthreads();

        // patch recon rows for corrected pixels (c = tid)
        for (int e = 0; e < ne; ++e) {
            const int m = g_fixlist[g0 + e];
            const int fi = sfi[e];
            out[(m >> 10) * 262144 + tid * 1024 + (m & 1023)] = proto[(fi << 8) + tid];
        }
        __syncthreads();
    }
}

// ---------------------------------------------------------------------------
extern "C" void kernel_launch(void* const* d_in, const int* in_sizes, int n_in,
                              void* d_out, int out_size)
{
    const float* x     = (const float*)d_in[0];
    const float* proto = (const float*)d_in[1];
    if (n_in >= 2 && in_sizes[0] == 512 * 256 && in_sizes[1] != 512 * 256) {
        proto = (const float*)d_in[0];
        x     = (const float*)d_in[1];
    }
    float* out = (float*)d_out;

    proto_prep_kernel<<<512, 256>>>(proto);
    xsplit_kernel<<<dim3(8, 32, 64), 256>>>(x);

    cudaFuncSetAttribute(protomatch_mma,
                         cudaFuncAttributeMaxDynamicSharedMemorySize, 181248);
    protomatch_mma<<<256, 512, 181248>>>(proto, out, (long long)out_size);

    fixup_kernel<<<64, 256>>>(x, proto, out, (long long)out_size);
}

// round 12
// speedup vs baseline: 2.6332x; 1.0054x over previous
#include <cuda_runtime.h>
#include <cuda_fp16.h>
#include <cstdint>
#include <math_constants.h>

// ---------------------------------------------------------------------------
// Device scratch (static: allocation-free)
// ---------------------------------------------------------------------------
__device__ __half g_a [65536 * 256];   // A pixel-major [m][c] = fp16(x)
__device__ __half g_bh[512 * 256];     // normalized proto fp16 [p][c]
__device__ float  g_pnf[512 * 256];    // normalized protos fp32 (for fixup)
__device__ int    g_fixlist[65536];
__device__ int    g_nfix;

__device__ __forceinline__ uint32_t smem_u32(const void* p) {
    uint32_t a;
    asm("{ .reg .u64 t; cvta.to.shared.u64 t, %1; cvt.u32.u64 %0, t; }"
        : "=r"(a) : "l"(p));
    return a;
}
__device__ __forceinline__ void cpa16(uint32_t dst, const void* src) {
    asm volatile("cp.async.cg.shared.global [%0], [%1], 16;"
                 :: "r"(dst), "l"(src));
}
#define LDSM_X4(r0,r1,r2,r3,addr) \
    asm volatile("ldmatrix.sync.aligned.m8n8.x4.shared.b16 {%0,%1,%2,%3}, [%4];" \
        : "=r"(r0),"=r"(r1),"=r"(r2),"=r"(r3) : "r"(addr))
#define MMA16816(d,a,b) \
    asm volatile("mma.sync.aligned.m16n8k16.row.col.f32.f16.f16.f32 " \
        "{%0,%1,%2,%3},{%4,%5,%6,%7},{%8,%9},{%0,%1,%2,%3};" \
        : "+f"(d[0]),"+f"(d[1]),"+f"(d[2]),"+f"(d[3]) \
        : "r"(a[0]),"r"(a[1]),"r"(a[2]),"r"(a[3]),"r"(b[0]),"r"(b[1]))

// fp16-GEMM absolute error < ~3.2e-4 std; 4e-3 threshold = ~12 sigma.
#define FIX_THRESH 4e-3f

// ---------------------------------------------------------------------------
// Prep 1: normalize protos -> fp16 + fp32 copies; reset fix counter
// ---------------------------------------------------------------------------
__global__ void proto_prep_kernel(const float* __restrict__ proto) {
    __shared__ float sred[8];
    const int p = blockIdx.x, c = threadIdx.x;
    float v = proto[(p << 8) + c];
    float ss = v * v;
    #pragma unroll
    for (int s = 16; s >= 1; s >>= 1) ss += __shfl_xor_sync(0xffffffffu, ss, s);
    if ((c & 31) == 0) sred[c >> 5] = ss;
    __syncthreads();
    float tot = 0.f;
    #pragma unroll
    for (int w = 0; w < 8; ++w) tot += sred[w];
    const float pn = v / fmaxf(sqrtf(tot), 1e-12f);
    g_pnf[(p << 8) + c] = pn;
    g_bh[(p << 8) + c] = __float2half(pn);
    if (p == 0 && c == 0) g_nfix = 0;
}

// ---------------------------------------------------------------------------
// Prep 2: transpose x [b][c][m] -> A [m][c] fp16, half2 stores.
// grid (4, 32, 64) = (64-ch tiles, 32-m tiles, batch), 256 threads.
// t row stride 66 (even) keeps &t[m][2*lane] 8B-aligned for float2 reads.
// ---------------------------------------------------------------------------
__global__ void xsplit_kernel(const float* __restrict__ x) {
    __shared__ float t[32][66];
    const int b = blockIdx.z, c0 = blockIdx.x << 6, m0 = blockIdx.y << 5;
    const int lane = threadIdx.x & 31, w = threadIdx.x >> 5;
    // load: warp w covers channels {w, w+8, ..., w+56}; 128B coalesced rows
    #pragma unroll
    for (int i = 0; i < 8; ++i) {
        int c = w + (i << 3);
        t[lane][c] = x[b * 262144 + (c0 + c) * 1024 + m0 + lane];
    }
    __syncthreads();
    // store: m = w + 8j; float2 smem read, half2 global write (128B/warp)
    __half2* ga2 = reinterpret_cast<__half2*>(g_a);
    #pragma unroll
    for (int j = 0; j < 4; ++j) {
        int m = w + (j << 3);
        float2 f = *reinterpret_cast<const float2*>(&t[m][lane << 1]);
        __half2 h = __halves2half2(__float2half(f.x), __float2half(f.y));
        ga2[((size_t)(b * 1024 + m0 + m) << 7) + (c0 >> 1) + lane] = h;
    }
}

// ---------------------------------------------------------------------------
// B slice loader (512 threads): 128 protos x 64 ch fp16 = 16KB into buf (t%3).
// Slice t: proto-chunk pc = t/4, k-chunk kb = t%4.
// ---------------------------------------------------------------------------
__device__ __forceinline__ void load_bslice(uint32_t Bsm, int t, int tid) {
    const int pc = t >> 2, kb = t & 3;
    const char* src0 = reinterpret_cast<const char*>(g_bh);
    const uint32_t dst = Bsm + (uint32_t)(t % 3) * 16384u;
    #pragma unroll
    for (int i = 0; i < 2; ++i) {
        int u = tid + (i << 9);          // 0..1023 16B units
        int r = u >> 3, c = u & 7;
        uint32_t o = (uint32_t)(r << 7) + (uint32_t)(c << 4);
        const char* src = src0 + (size_t)(pc * 128 + r) * 512 + kb * 128 + (c << 4);
        cpa16(dst + (o ^ ((o >> 3) & 0x70)), src);
    }
}

// ---------------------------------------------------------------------------
// Main: 256 blocks x 256 pixels, 512 threads (16 warps, 4m x 4n warp grid,
// 64x32 tile/warp). A (256x256 fp16, 128KB) staged once; 16 B slices (16KB)
// 3-stage pipelined. fp16 GEMM, fp32 acc, top-2 + fused gather epilogue.
// ---------------------------------------------------------------------------
__global__ __launch_bounds__(512, 1)
void protomatch_mma(const float* __restrict__ proto,
                    float* __restrict__ out, long long out_size)
{
    extern __shared__ char dsm[];
    const uint32_t dynb = smem_u32(dsm);
    const uint32_t base = (dynb + 1023u) & ~1023u;
    char* base_g = dsm + (base - dynb);
    const uint32_t Asm = base;            // 131072 bytes (4 chunks x 32KB)
    const uint32_t Bsm = base + 131072u;  // 49152 bytes (3 bufs x 16KB)

    const int tid = threadIdx.x, lane = tid & 31, wid = tid >> 5;
    const int warp_m = wid & 3, warp_n = wid >> 2;   // 4 x 4
    const int m0 = blockIdx.x << 8;      // 256 pixels per block
    const int b = m0 >> 10, n0 = m0 & 1023;

    // ---- stage A (256 rows x 256 fp16 = 128KB) + first two B slices ----
    const char* Ag = reinterpret_cast<const char*>(g_a);
    #pragma unroll
    for (int i = 0; i < 16; ++i) {
        int u = tid + (i << 9);          // 0..8191 16B units
        int s = u >> 11;                 // chunk 0..3 (2048 units each)
        int r = (u >> 3) & 255;          // row 0..255
        int c = u & 7;                   // 16B col 0..7
        uint32_t o = (uint32_t)(r << 7) + (uint32_t)(c << 4);
        cpa16(Asm + (s << 15) + (o ^ ((o >> 3) & 0x70)),
              Ag + (size_t)(m0 + r) * 512 + (s << 7) + (c << 4));
    }
    load_bslice(Bsm, 0, tid);
    asm volatile("cp.async.commit_group;");
    load_bslice(Bsm, 1, tid);
    asm volatile("cp.async.commit_group;");

    // per-lane ldmatrix address components: 4 m-tiles of 16 rows per warp
    uint32_t aoff[4], aswz[4];
    #pragma unroll
    for (int mt = 0; mt < 4; ++mt) {
        int rowA = warp_m * 64 + mt * 16 + (lane & 15);
        aoff[mt] = (uint32_t)rowA << 7;
        aswz[mt] = (uint32_t)(rowA & 7);
    }
    const uint32_t alc = (uint32_t)(lane >> 4);        // k-half select for A

    uint32_t boff[2], bswz[2];
    #pragma unroll
    for (int nt2 = 0; nt2 < 2; ++nt2) {
        int rowB = warp_n * 32 + nt2 * 16 + ((lane >> 4) << 3) + (lane & 7);
        boff[nt2] = (uint32_t)rowB << 7;
        bswz[nt2] = (uint32_t)(rowB & 7);
    }
    const uint32_t blc = (uint32_t)((lane >> 3) & 1);  // k-half select for B

    float acc[4][4][4];
    float t1v[8], t2v[8];
    int   t1i[8];
    #pragma unroll
    for (int s = 0; s < 8; ++s) { t1v[s] = -CUDART_INF_F; t2v[s] = -CUDART_INF_F; t1i[s] = 0; }

    for (int t = 0; t < 16; ++t) {
        const int pc = t >> 2, kb = t & 3;
        if (kb == 0) {
            #pragma unroll
            for (int i = 0; i < 4; ++i)
                #pragma unroll
                for (int j = 0; j < 4; ++j)
                    #pragma unroll
                    for (int q = 0; q < 4; ++q) acc[i][j][q] = 0.f;
        }
        // pipeline: wait(tile t ready) -> sync -> issue copy t+2 -> compute
        if (t < 15) asm volatile("cp.async.wait_group 1;");
        else        asm volatile("cp.async.wait_group 0;");
        __syncthreads();
        if (t + 2 < 16) {
            load_bslice(Bsm, t + 2, tid);
            asm volatile("cp.async.commit_group;");
        }

        const uint32_t Ab = Asm + ((uint32_t)kb << 15);
        const uint32_t Bb = Bsm + (uint32_t)(t % 3) * 16384u;

        #pragma unroll
        for (int k16 = 0; k16 < 4; ++k16) {
            uint32_t ra[4][4];
            #pragma unroll
            for (int mt = 0; mt < 4; ++mt) {
                uint32_t c16 = (uint32_t)(k16 << 1) + alc;
                LDSM_X4(ra[mt][0], ra[mt][1], ra[mt][2], ra[mt][3],
                        Ab + aoff[mt] + ((c16 ^ aswz[mt]) << 4));
            }
            #pragma unroll
            for (int nt2 = 0; nt2 < 2; ++nt2) {
                uint32_t c16 = (uint32_t)(k16 << 1) + blc;
                uint32_t rb[4];
                LDSM_X4(rb[0], rb[1], rb[2], rb[3],
                        Bb + boff[nt2] + ((c16 ^ bswz[nt2]) << 4));
                #pragma unroll
                for (int mt = 0; mt < 4; ++mt) {
                    MMA16816(acc[mt][2*nt2+0], ra[mt], (rb + 0));
                    MMA16816(acc[mt][2*nt2+1], ra[mt], (rb + 2));
                }
            }
        }

        if (kb == 3) {     // fold chunk pc into running top-2
            #pragma unroll
            for (int mt = 0; mt < 4; ++mt)
                #pragma unroll
                for (int rh = 0; rh < 2; ++rh) {
                    int sl = mt * 2 + rh;
                    #pragma unroll
                    for (int nt = 0; nt < 4; ++nt)
                        #pragma unroll
                        for (int e = 0; e < 2; ++e) {
                            float v = acc[mt][nt][rh * 2 + e];
                            int col = (pc << 7) + (warp_n << 5) + (nt << 3)
                                    + ((lane & 3) << 1) + e;
                            if (v > t1v[sl]) { t2v[sl] = t1v[sl]; t1v[sl] = v; t1i[sl] = col; }
                            else if (v > t2v[sl]) t2v[sl] = v;
                        }
                }
        }
    }
    __syncthreads();

    // ---- cross-lane/warp reduction via smem (reuse A region) ----
    float* sv1 = reinterpret_cast<float*>(base_g);            // [256][16]
    int*   si1 = reinterpret_cast<int*>(base_g + 16384);
    float* sv2 = reinterpret_cast<float*>(base_g + 32768);
    int*   sIdx = reinterpret_cast<int*>(base_g + 49152);     // [256]
    #pragma unroll
    for (int mt = 0; mt < 4; ++mt)
        #pragma unroll
        for (int rh = 0; rh < 2; ++rh) {
            int sl = mt * 2 + rh;
            int row = warp_m * 64 + mt * 16 + rh * 8 + (lane >> 2);
            int cand = (warp_n << 2) + (lane & 3);
            sv1[row * 16 + cand] = t1v[sl];
            si1[row * 16 + cand] = t1i[sl];
            sv2[row * 16 + cand] = t2v[sl];
        }
    __syncthreads();

    if (tid < 256) {
        float v1 = -CUDART_INF_F, v2 = -CUDART_INF_F;
        int i1 = 0x7fffffff;
        #pragma unroll
        for (int c = 0; c < 16; ++c) {
            float cv1 = sv1[tid * 16 + c], cv2 = sv2[tid * 16 + c];
            int   ci1 = si1[tid * 16 + c];
            if (cv1 > v1 || (cv1 == v1 && ci1 < i1)) {
                v2 = fmaxf(v1, cv2); v1 = cv1; i1 = ci1;
            } else {
                v2 = fmaxf(v2, cv1);
            }
        }
        const int m = m0 + tid;
        sIdx[tid] = i1;
        if (out_size > 16777216LL) out[16777216 + m] = (float)i1;
        if (v1 - v2 < FIX_THRESH) {
            int pos = atomicAdd(&g_nfix, 1);
            g_fixlist[pos] = m;
        }
    }
    __syncthreads();

    // ---- fused gather: recon[b,c,h,w] = proto[idx][c], coalesced ----
    const int n4 = tid & 63;   // float4 col within 256-pixel tile
    const int ph = tid >> 6;   // channel phase 0..7
    const float* r0 = proto + (sIdx[(n4 << 2) + 0] << 8);
    const float* r1 = proto + (sIdx[(n4 << 2) + 1] << 8);
    const float* r2 = proto + (sIdx[(n4 << 2) + 2] << 8);
    const float* r3 = proto + (sIdx[(n4 << 2) + 3] << 8);
    float4* Og = reinterpret_cast<float4*>(out) + (b * 65536 + (n0 >> 2) + n4);
    #pragma unroll 4
    for (int c = ph; c < 256; c += 8)
        Og[c * 256] = make_float4(r0[c], r1[c], r2[c], r3[c]);
}

// ---------------------------------------------------------------------------
// Fixup: exact fp32 argmax for flagged pixels, 4 entries/block, grid 256;
// patches the recon rows of corrected pixels.
// ---------------------------------------------------------------------------
__global__ __launch_bounds__(256)
void fixup_kernel(const float* __restrict__ x, const float* __restrict__ proto,
                  float* __restrict__ out, long long out_size)
{
    __shared__ __align__(16) float xs[4][260];
    __shared__ float rbv[4][8];
    __shared__ int   rbi[4][8];
    __shared__ int   sfi[4];
    const int tid = threadIdx.x, lane = tid & 31, wid = tid >> 5;
    const int nfix = g_nfix;

    for (int g0 = blockIdx.x * 4; g0 < nfix; g0 += gridDim.x * 4) {
        const int ne = min(4, nfix - g0);
        for (int i = tid; i < (ne << 8); i += 256) {
            int e = i >> 8, c = i & 255;
            int m = g_fixlist[g0 + e];
            xs[e][c] = x[(m >> 10) * 262144 + c * 1024 + (m & 1023)];
        }
        __syncthreads();

        float bv[4]; int bi[4];
        #pragma unroll
        for (int e = 0; e < 4; ++e) { bv[e] = -CUDART_INF_F; bi[e] = 0; }

        #pragma unroll
        for (int h = 0; h < 2; ++h) {
            const int p = tid + (h << 8);
            const float4* pr = reinterpret_cast<const float4*>(g_pnf + (p << 8));
            float acc[4];
            #pragma unroll
            for (int e = 0; e < 4; ++e) acc[e] = 0.f;
            #pragma unroll 4
            for (int c4 = 0; c4 < 64; ++c4) {
                float4 pv = pr[c4];
                #pragma unroll
                for (int e = 0; e < 4; ++e) {
                    float4 xv = reinterpret_cast<const float4*>(xs[e])[c4];
                    acc[e] = fmaf(pv.x, xv.x, acc[e]);
                    acc[e] = fmaf(pv.y, xv.y, acc[e]);
                    acc[e] = fmaf(pv.z, xv.z, acc[e]);
                    acc[e] = fmaf(pv.w, xv.w, acc[e]);
                }
            }
            #pragma unroll
            for (int e = 0; e < 4; ++e)
                if (acc[e] > bv[e]) { bv[e] = acc[e]; bi[e] = p; }  // ascending p
        }

        #pragma unroll
        for (int e = 0; e < 4; ++e) {
            float v = bv[e]; int ix = bi[e];
            #pragma unroll
            for (int s = 16; s >= 1; s >>= 1) {
                float ov = __shfl_xor_sync(0xffffffffu, v, s);
                int   oi = __shfl_xor_sync(0xffffffffu, ix, s);
                if (ov > v || (ov == v && oi < ix)) { v = ov; ix = oi; }
            }
            if (lane == 0) { rbv[e][wid] = v; rbi[e][wid] = ix; }
        }
        __syncthreads();

        if (tid < ne) {
            float fv = rbv[tid][0]; int fi = rbi[tid][0];
            #pragma unroll
            for (int w = 1; w < 8; ++w)
                if (rbv[tid][w] > fv || (rbv[tid][w] == fv && rbi[tid][w] < fi)) {
                    fv = rbv[tid][w]; fi = rbi[tid][w];
                }
            sfi[tid] = fi;
            const int m = g_fixlist[g0 + tid];
            if (out_size > 16777216LL) out[16777216 + m] = (float)fi;
        }
        __syncthreads();

        // patch recon rows for corrected pixels (c = tid)
        for (int e = 0; e < ne; ++e) {
            const int m = g_fixlist[g0 + e];
            const int fi = sfi[e];
            out[(m >> 10) * 262144 + tid * 1024 + (m & 1023)] = proto[(fi << 8) + tid];
        }
        __syncthreads();
    }
}

// ---------------------------------------------------------------------------
extern "C" void kernel_launch(void* const* d_in, const int* in_sizes, int n_in,
                              void* d_out, int out_size)
{
    const float* x     = (const float*)d_in[0];
    const float* proto = (const float*)d_in[1];
    if (n_in >= 2 && in_sizes[0] == 512 * 256 && in_sizes[1] != 512 * 256) {
        proto = (const float*)d_in[0];
        x     = (const float*)d_in[1];
    }
    float* out = (float*)d_out;

    proto_prep_kernel<<<512, 256>>>(proto);
    xsplit_kernel<<<dim3(4, 32, 64), 256>>>(x);

    cudaFuncSetAttribute(protomatch_mma,
                         cudaFuncAttributeMaxDynamicSharedMemorySize, 181248);
    protomatch_mma<<<256, 512, 181248>>>(proto, out, (long long)out_size);

    fixup_kernel<<<256, 256>>>(x, proto, out, (long long)out_size);
}